// round 7
// baseline (speedup 1.0000x reference)
#include <cuda_runtime.h>
#include <cstdint>
#include <math.h>

typedef unsigned long long ull;

#define MTOK 32768

// ---------------- static scratch ----------------
__device__ float g_pre_wf[MTOK * 512];
__device__ float g_pre_wb[MTOK * 512];
__device__ float g_pre_sf[MTOK * 512];
__device__ float g_pre_sb[MTOK * 512];
__device__ float g_fo[MTOK * 256];
__device__ float g_fs[MTOK * 256];

// ---------------- helpers ----------------
__device__ __forceinline__ ull ffma2(ull a, ull b, ull c) {
    ull d; asm("fma.rn.f32x2 %0,%1,%2,%3;" : "=l"(d) : "l"(a), "l"(b), "l"(c)); return d;
}
__device__ __forceinline__ ull pack2(float x, float y) {
    ull r; asm("mov.b64 %0,{%1,%2};" : "=l"(r) : "f"(x), "f"(y)); return r;
}
__device__ __forceinline__ float2 unpack2(ull v) {
    float2 r; asm("mov.b64 {%0,%1},%2;" : "=f"(r.x), "=f"(r.y) : "l"(v)); return r;
}
__device__ __forceinline__ uint32_t smem_u32(const void* p) {
    uint32_t a;
    asm("{ .reg .u64 t; cvta.to.shared.u64 t, %1; cvt.u32.u64 %0, t; }" : "=r"(a) : "l"(p));
    return a;
}
__device__ __forceinline__ uint32_t ctarank() {
    uint32_t r; asm("mov.u32 %0, %%cluster_ctarank;" : "=r"(r)); return r;
}
__device__ __forceinline__ uint32_t mapa_u32(uint32_t addr, uint32_t rank) {
    uint32_t r; asm("mapa.shared::cluster.u32 %0, %1, %2;" : "=r"(r) : "r"(addr), "r"(rank)); return r;
}
__device__ __forceinline__ void mbar_init(uint32_t a, uint32_t cnt) {
    asm volatile("mbarrier.init.shared.b64 [%0], %1;" :: "r"(a), "r"(cnt) : "memory");
}
__device__ __forceinline__ void st_cluster_f32(uint32_t a, float v) {
    asm volatile("st.shared::cluster.f32 [%0], %1;" :: "r"(a), "f"(v) : "memory");
}
__device__ __forceinline__ void mbar_arrive_local(uint32_t a) {
    asm volatile("mbarrier.arrive.shared.b64 _, [%0];" :: "r"(a) : "memory");
}
__device__ __forceinline__ void mbar_arrive_rel_cluster(uint32_t a) {
    asm volatile("mbarrier.arrive.release.cluster.shared::cluster.b64 _, [%0];" :: "r"(a) : "memory");
}
__device__ __forceinline__ void mbar_wait(uint32_t a, uint32_t parity) {
    asm volatile(
        "{\n\t.reg .pred P;\n\t"
        "WL_%=:\n\t"
        "mbarrier.try_wait.parity.acquire.cluster.shared::cta.b64 P, [%0], %1, 0x989680;\n\t"
        "@P bra.uni WD_%=;\n\t"
        "bra.uni WL_%=;\n\t"
        "WD_%=:\n\t}"
        :: "r"(a), "r"(parity) : "memory");
}
__device__ __forceinline__ void cluster_sync_() {
    asm volatile("barrier.cluster.arrive.aligned;" ::: "memory");
    asm volatile("barrier.cluster.wait.aligned;" ::: "memory");
}
__device__ __forceinline__ float sigm(float x) { return 1.f / (1.f + __expf(-x)); }

// ---------------- GEMM ----------------
// MODE 0: C[m][n] = sum_k A[idx[m]][k]*W[n][k] + bias[n]          (pre-activations)
// MODE 1: A row = concat(fo[m], fs[m]) (K=512); gate epilogue:
//         s = sigmoid(acc + bias[n]); C[m][n] = s*fo[m][n] + (1-s)*fs[m][n]
template <int MODE>
__global__ __launch_bounds__(256, 2)
void gemm_k(const int* __restrict__ idx, const float* __restrict__ A,
            const float* __restrict__ W, const float* __restrict__ bias,
            float* __restrict__ C, int K, int ldc,
            const float* __restrict__ fo, const float* __restrict__ fs)
{
    __shared__ __align__(16) ull   As2[16][128];   // (a,a) duplicated pairs
    __shared__ __align__(16) float Bs[16][128];
    const int tid = threadIdx.x;
    const int m0 = blockIdx.x * 128, n0 = blockIdx.y * 128;
    const int lr = tid >> 2, lc = (tid & 3) << 2;
    const int tx = tid & 15, ty = tid >> 4;

    const float *a0p = nullptr, *a1p = nullptr;
    if (MODE == 0) {
        a0p = A + (size_t)__ldg(idx + m0 + lr) * K + lc;
        a1p = A + (size_t)__ldg(idx + m0 + lr + 64) * K + lc;
    }
    const float* b0p = W + (size_t)(n0 + lr) * K + lc;
    const float* b1p = W + (size_t)(n0 + lr + 64) * K + lc;

    ull acc[8][4];
#pragma unroll
    for (int i = 0; i < 8; i++)
#pragma unroll
        for (int j = 0; j < 4; j++) acc[i][j] = 0ULL;

    for (int k0 = 0; k0 < K; k0 += 16) {
        float4 a0, a1;
        if (MODE == 0) {
            a0 = *(const float4*)(a0p + k0);
            a1 = *(const float4*)(a1p + k0);
        } else {
            const float* base = (k0 < 256) ? fo : fs;
            int kk = (k0 < 256) ? k0 : (k0 - 256);
            a0 = *(const float4*)(base + (size_t)(m0 + lr) * 256 + kk + lc);
            a1 = *(const float4*)(base + (size_t)(m0 + lr + 64) * 256 + kk + lc);
        }
        float4 b0 = *(const float4*)(b0p + k0);
        float4 b1 = *(const float4*)(b1p + k0);
        __syncthreads();
        As2[lc + 0][lr] = pack2(a0.x, a0.x); As2[lc + 1][lr] = pack2(a0.y, a0.y);
        As2[lc + 2][lr] = pack2(a0.z, a0.z); As2[lc + 3][lr] = pack2(a0.w, a0.w);
        As2[lc + 0][lr + 64] = pack2(a1.x, a1.x); As2[lc + 1][lr + 64] = pack2(a1.y, a1.y);
        As2[lc + 2][lr + 64] = pack2(a1.z, a1.z); As2[lc + 3][lr + 64] = pack2(a1.w, a1.w);
        Bs[lc + 0][lr] = b0.x; Bs[lc + 1][lr] = b0.y; Bs[lc + 2][lr] = b0.z; Bs[lc + 3][lr] = b0.w;
        Bs[lc + 0][lr + 64] = b1.x; Bs[lc + 1][lr + 64] = b1.y; Bs[lc + 2][lr + 64] = b1.z; Bs[lc + 3][lr + 64] = b1.w;
        __syncthreads();
#pragma unroll
        for (int k = 0; k < 16; k++) {
            const ulonglong2* ap = (const ulonglong2*)&As2[k][ty * 8];
            ulonglong2 aA = ap[0], aB = ap[1], aC = ap[2], aD = ap[3];
            const ulonglong2* bp = (const ulonglong2*)&Bs[k][tx * 8];
            ulonglong2 bA = bp[0], bB = bp[1];
            ull av[8] = {aA.x, aA.y, aB.x, aB.y, aC.x, aC.y, aD.x, aD.y};
            ull bv[4] = {bA.x, bA.y, bB.x, bB.y};
#pragma unroll
            for (int i = 0; i < 8; i++)
#pragma unroll
                for (int j = 0; j < 4; j++)
                    acc[i][j] = ffma2(av[i], bv[j], acc[i][j]);
        }
    }
#pragma unroll
    for (int i = 0; i < 8; i++) {
        int m = m0 + ty * 8 + i;
#pragma unroll
        for (int j = 0; j < 4; j++) {
            int n = n0 + tx * 8 + 2 * j;
            float2 v = unpack2(acc[i][j]);
            if (MODE == 0) {
                float2 o;
                o.x = v.x + __ldg(bias + n);
                o.y = v.y + __ldg(bias + n + 1);
                *(float2*)(C + (size_t)m * ldc + n) = o;
            } else {
                float2 fov = *(const float2*)(fo + (size_t)m * 256 + n);
                float2 fsv = *(const float2*)(fs + (size_t)m * 256 + n);
                float s0 = sigm(v.x + __ldg(bias + n));
                float s1 = sigm(v.y + __ldg(bias + n + 1));
                float2 o;
                o.x = s0 * fov.x + (1.f - s0) * fsv.x;
                o.y = s1 * fov.y + (1.f - s1) * fsv.y;
                *(float2*)(C + (size_t)m * 256 + n) = o;
            }
        }
    }
}

// ---------------- BiLSTM recurrence (2-CTA cluster per seq-dir) ----------------
// grid.x = nseq*2*2 CTAs, cluster (2,1,1). cid=blockIdx.x/2: dir=cid&1, seq=cid>>1.
// CTA rank r owns hidden units [r*64, r*64+64): its 256 threads own gate rows
// q*128 + r*64 + u (q=tid/64, u=tid%64), weights in registers.
// Barrier protocol: double-buffered h, one mbarrier per buffer, count 512
// (256 local arrivals + 256 remote release-arrivals). Final step issues NO
// remote traffic; trailing cluster.sync guarantees no in-flight remote SMEM
// access targets an exited CTA (the R2-R5 ULF).
__global__ __launch_bounds__(256, 1)
void lstm_k(const float* __restrict__ preF, const float* __restrict__ preB,
            const float* __restrict__ WhhF, const float* __restrict__ WhhB,
            float* __restrict__ outb, int L)
{
    __shared__ __align__(16) float h_sh[2][128];
    __shared__ float gacc[256];
    __shared__ __align__(8) ull bars[2];
    const int t = threadIdx.x;
    const int cid = blockIdx.x >> 1;
    const uint32_t r = ctarank();
    const int dir = cid & 1;
    const int seq = cid >> 1;
    const float* pre = dir ? preB : preF;
    const float* Whh = dir ? WhhB : WhhF;
    const int q = t >> 6, u = t & 63;
    const int grow = q * 128 + (int)r * 64 + u;

    ull w2[64];
    {
        const ulonglong2* wr = (const ulonglong2*)(Whh + (size_t)grow * 128);
#pragma unroll
        for (int i = 0; i < 32; i++) { ulonglong2 v = wr[i]; w2[2 * i] = v.x; w2[2 * i + 1] = v.y; }
    }
    if (t < 128) { h_sh[0][t] = 0.f; h_sh[1][t] = 0.f; }
    uint32_t bar0 = smem_u32(&bars[0]), bar1 = smem_u32(&bars[1]);
    if (t == 0) { mbar_init(bar0, 512); mbar_init(bar1, 512); }
    __syncthreads();
    cluster_sync_();
    const uint32_t peer = r ^ 1u;
    const uint32_t rbar0 = mapa_u32(bar0, peer), rbar1 = mapa_u32(bar1, peer);
    const uint32_t hb0 = smem_u32(&h_sh[0][0]), hb1 = smem_u32(&h_sh[1][0]);
    const size_t seqbase = (size_t)seq * L;

    int ph0 = 0, ph1 = 0;
    float c = 0.f;
    float pv0 = __ldg(pre + (seqbase + (dir ? (L - 1) : 0)) * 512 + grow);
    float pv1 = (L > 1) ? __ldg(pre + (seqbase + (dir ? (L - 2) : 1)) * 512 + grow) : 0.f;

    for (int s = 0; s < L; s++) {
        int b = s & 1;
        if (s > 0) {
            if (b) { mbar_wait(bar1, ph1); ph1 ^= 1; }
            else   { mbar_wait(bar0, ph0); ph0 ^= 1; }
        }
        const ull* h2 = (const ull*)h_sh[b];
        ull a2 = 0ULL;
#pragma unroll
        for (int k = 0; k < 64; k++) a2 = ffma2(w2[k], h2[k], a2);
        float2 av = unpack2(a2);
        float acc = pv0 + av.x + av.y;
        pv0 = pv1;
        int s2 = s + 2;
        pv1 = (s2 < L) ? __ldg(pre + (seqbase + (dir ? (L - 1 - s2) : s2)) * 512 + grow) : 0.f;
        gacc[t] = acc;
        __syncthreads();
        int nb = b ^ 1;
        bool last = (s == L - 1);
        if (t < 64) {
            float gi = gacc[t], gf = gacc[64 + t], gg = gacc[128 + t], go = gacc[192 + t];
            c = sigm(gf) * c + sigm(gi) * tanhf(gg);
            float h = sigm(go) * tanhf(c);
            int j = (int)r * 64 + t;
            int tp = dir ? (L - 1 - s) : s;
            outb[(seqbase + tp) * 256 + dir * 128 + j] = h;
            if (!last) {
                h_sh[nb][j] = h;
                st_cluster_f32(mapa_u32((nb ? hb1 : hb0) + 4u * j, peer), h);
            }
        }
        if (!last) {
            mbar_arrive_local(nb ? bar1 : bar0);
            mbar_arrive_rel_cluster(nb ? rbar1 : rbar0);
        }
    }
    // Required: no CTA may exit while a peer's remote SMEM access targeting it
    // could still be in flight.
    cluster_sync_();
}

// ---------------- launch ----------------
static void launch_lstm(int ncta, const float* pf, const float* pb,
                        const float* wf, const float* wb, float* outb, int L)
{
    cudaLaunchConfig_t cfg = {};
    cfg.gridDim = dim3((unsigned)ncta, 1, 1);
    cfg.blockDim = dim3(256, 1, 1);
    cfg.dynamicSmemBytes = 0;
    cfg.stream = 0;
    cudaLaunchAttribute attr[1];
    attr[0].id = cudaLaunchAttributeClusterDimension;
    attr[0].val.clusterDim.x = 2; attr[0].val.clusterDim.y = 1; attr[0].val.clusterDim.z = 1;
    cfg.attrs = attr; cfg.numAttrs = 1;
    cudaLaunchKernelEx(&cfg, lstm_k, pf, pb, wf, wb, outb, L);
}

extern "C" void kernel_launch(void* const* d_in, const int* in_sizes, int n_in,
                              void* d_out, int out_size)
{
    (void)in_sizes; (void)out_size;
    const int off = (n_in >= 18) ? 1 : 0;   // skip seq_len scalar if present
    const int*   widx   = (const int*)d_in[0];
    const int*   sidx   = (const int*)d_in[1];
    const float* E      = (const float*)d_in[2 + off];
    const float* Wih_f  = (const float*)d_in[3 + off];
    const float* Whh_f  = (const float*)d_in[4 + off];
    const float* b_f    = (const float*)d_in[5 + off];
    const float* Wih_b  = (const float*)d_in[6 + off];
    const float* Whh_b  = (const float*)d_in[7 + off];
    const float* b_b    = (const float*)d_in[8 + off];
    const float* sWih_f = (const float*)d_in[9 + off];
    const float* sWhh_f = (const float*)d_in[10 + off];
    const float* sb_f   = (const float*)d_in[11 + off];
    const float* sWih_b = (const float*)d_in[12 + off];
    const float* sWhh_b = (const float*)d_in[13 + off];
    const float* sb_b   = (const float*)d_in[14 + off];
    const float* gW     = (const float*)d_in[15 + off];
    const float* gb     = (const float*)d_in[16 + off];
    float* out = (float*)d_out;

    float *pwf, *pwb, *psf, *psb, *fo, *fs;
    cudaGetSymbolAddress((void**)&pwf, g_pre_wf);
    cudaGetSymbolAddress((void**)&pwb, g_pre_wb);
    cudaGetSymbolAddress((void**)&psf, g_pre_sf);
    cudaGetSymbolAddress((void**)&psb, g_pre_sb);
    cudaGetSymbolAddress((void**)&fo, g_fo);
    cudaGetSymbolAddress((void**)&fs, g_fs);

    dim3 blk(256, 1, 1);
    dim3 gpre(MTOK / 128, 4, 1);
    // 4 pre-activation GEMMs (gather-fused embedding)
    gemm_k<0><<<gpre, blk>>>(widx, E, Wih_f, b_f, pwf, 768, 512, nullptr, nullptr);
    gemm_k<0><<<gpre, blk>>>(widx, E, Wih_b, b_b, pwb, 768, 512, nullptr, nullptr);
    gemm_k<0><<<gpre, blk>>>(sidx, E, sWih_f, sb_f, psf, 768, 512, nullptr, nullptr);
    gemm_k<0><<<gpre, blk>>>(sidx, E, sWih_b, sb_b, psb, 768, 512, nullptr, nullptr);
    // word BiLSTM: 32 seqs * 2 dirs * 2 CTAs ; L=1024
    launch_lstm(32 * 2 * 2, pwf, pwb, Whh_f, Whh_b, fo, 1024);
    // sent BiLSTM: 512 seqs * 2 dirs * 2 CTAs ; L=64
    launch_lstm(512 * 2 * 2, psf, psb, sWhh_f, sWhh_b, fs, 64);
    // gate GEMM + blend
    dim3 ggate(MTOK / 128, 2, 1);
    gemm_k<1><<<ggate, blk>>>(nullptr, nullptr, gW, gb, out, 512, 256, fo, fs);
}

// round 9
// speedup vs baseline: 1.0437x; 1.0437x over previous
#include <cuda_runtime.h>
#include <cstdint>
#include <math.h>

typedef unsigned long long ull;

#define MTOK 32768

// ---------------- static scratch ----------------
__device__ float g_pre_wf[MTOK * 512];
__device__ float g_pre_wb[MTOK * 512];
__device__ float g_pre_sf[MTOK * 512];
__device__ float g_pre_sb[MTOK * 512];
__device__ float g_fo[MTOK * 256];
__device__ float g_fs[MTOK * 256];

// ---------------- helpers ----------------
__device__ __forceinline__ ull ffma2(ull a, ull b, ull c) {
    ull d; asm("fma.rn.f32x2 %0,%1,%2,%3;" : "=l"(d) : "l"(a), "l"(b), "l"(c)); return d;
}
__device__ __forceinline__ ull pack2(float x, float y) {
    ull r; asm("mov.b64 %0,{%1,%2};" : "=l"(r) : "f"(x), "f"(y)); return r;
}
__device__ __forceinline__ float2 unpack2(ull v) {
    float2 r; asm("mov.b64 {%0,%1},%2;" : "=f"(r.x), "=f"(r.y) : "l"(v)); return r;
}
__device__ __forceinline__ uint32_t smem_u32(const void* p) {
    uint32_t a;
    asm("{ .reg .u64 t; cvta.to.shared.u64 t, %1; cvt.u32.u64 %0, t; }" : "=r"(a) : "l"(p));
    return a;
}
__device__ __forceinline__ uint32_t ctarank() {
    uint32_t r; asm("mov.u32 %0, %%cluster_ctarank;" : "=r"(r)); return r;
}
__device__ __forceinline__ uint32_t mapa_u32(uint32_t addr, uint32_t rank) {
    uint32_t r; asm("mapa.shared::cluster.u32 %0, %1, %2;" : "=r"(r) : "r"(addr), "r"(rank)); return r;
}
__device__ __forceinline__ void mbar_init(uint32_t a, uint32_t cnt) {
    asm volatile("mbarrier.init.shared.b64 [%0], %1;" :: "r"(a), "r"(cnt) : "memory");
}
__device__ __forceinline__ void st_cluster_f32(uint32_t a, float v) {
    asm volatile("st.shared::cluster.f32 [%0], %1;" :: "r"(a), "f"(v) : "memory");
}
__device__ __forceinline__ void mbar_arrive_local(uint32_t a) {
    asm volatile("mbarrier.arrive.shared.b64 _, [%0];" :: "r"(a) : "memory");
}
__device__ __forceinline__ void mbar_arrive_rel_cluster(uint32_t a) {
    asm volatile("mbarrier.arrive.release.cluster.shared::cluster.b64 _, [%0];" :: "r"(a) : "memory");
}
__device__ __forceinline__ void mbar_wait(uint32_t a, uint32_t parity) {
    asm volatile(
        "{\n\t.reg .pred P;\n\t"
        "WL_%=:\n\t"
        "mbarrier.try_wait.parity.acquire.cluster.shared::cta.b64 P, [%0], %1, 0x989680;\n\t"
        "@P bra.uni WD_%=;\n\t"
        "bra.uni WL_%=;\n\t"
        "WD_%=:\n\t}"
        :: "r"(a), "r"(parity) : "memory");
}
__device__ __forceinline__ void cluster_sync_() {
    asm volatile("barrier.cluster.arrive.aligned;" ::: "memory");
    asm volatile("barrier.cluster.wait.aligned;" ::: "memory");
}
__device__ __forceinline__ float sigm(float x) {
    return __fdividef(1.f, 1.f + __expf(-x));
}
// overflow-safe fast tanh: tanh(x) = sign(x) * (1-e)/(1+e), e = exp(-2|x|) in (0,1]
__device__ __forceinline__ float tanh_fast(float x) {
    float ax = fabsf(x);
    float e = __expf(-2.f * ax);
    float t = __fdividef(1.f - e, 1.f + e);
    return copysignf(t, x);
}

// ---------------- GEMM (register-staged prefetch + ping-pong smem) ----------------
// MODE 0: C[m][n] = sum_k A[idx[m]][k]*W[n][k] + bias[n]   (KC=768, ldc=512)
// MODE 1: A row = concat(fo[m], fs[m]) (KC=512); gate epilogue, ldc=256
template <int MODE, int KC>
__global__ __launch_bounds__(256, 2)
void gemm_k(const int* __restrict__ idx, const float* __restrict__ A,
            const float* __restrict__ W, const float* __restrict__ bias,
            float* __restrict__ C,
            const float* __restrict__ fo, const float* __restrict__ fs)
{
    __shared__ __align__(16) ull   As2[2][16][128];   // (a,a) duplicated pairs
    __shared__ __align__(16) float Bs[2][16][128];
    const int tid = threadIdx.x;
    const int m0 = blockIdx.x * 128, n0 = blockIdx.y * 128;
    const int lr = tid >> 2, lc = (tid & 3) << 2;
    const int tx = tid & 15, ty = tid >> 4;
    constexpr int LDC = (MODE == 0) ? 512 : 256;
    constexpr int NT = KC / 16;

    const float *a0p = nullptr, *a1p = nullptr;
    if (MODE == 0) {
        a0p = A + (size_t)__ldg(idx + m0 + lr) * KC + lc;
        a1p = A + (size_t)__ldg(idx + m0 + lr + 64) * KC + lc;
    }
    const float* b0p = W + (size_t)(n0 + lr) * KC + lc;
    const float* b1p = W + (size_t)(n0 + lr + 64) * KC + lc;

    ull acc[8][4];
#pragma unroll
    for (int i = 0; i < 8; i++)
#pragma unroll
        for (int j = 0; j < 4; j++) acc[i][j] = 0ULL;

    auto ldTile = [&](int k0, float4& a0, float4& a1, float4& b0, float4& b1) {
        if (MODE == 0) {
            a0 = *(const float4*)(a0p + k0);
            a1 = *(const float4*)(a1p + k0);
        } else {
            const float* base = (k0 < 256) ? fo : fs;
            int kk = (k0 < 256) ? k0 : (k0 - 256);
            a0 = *(const float4*)(base + (size_t)(m0 + lr) * 256 + kk + lc);
            a1 = *(const float4*)(base + (size_t)(m0 + lr + 64) * 256 + kk + lc);
        }
        b0 = *(const float4*)(b0p + k0);
        b1 = *(const float4*)(b1p + k0);
    };
    auto stTile = [&](int buf, const float4& a0, const float4& a1,
                      const float4& b0, const float4& b1) {
        As2[buf][lc + 0][lr] = pack2(a0.x, a0.x); As2[buf][lc + 1][lr] = pack2(a0.y, a0.y);
        As2[buf][lc + 2][lr] = pack2(a0.z, a0.z); As2[buf][lc + 3][lr] = pack2(a0.w, a0.w);
        As2[buf][lc + 0][lr + 64] = pack2(a1.x, a1.x); As2[buf][lc + 1][lr + 64] = pack2(a1.y, a1.y);
        As2[buf][lc + 2][lr + 64] = pack2(a1.z, a1.z); As2[buf][lc + 3][lr + 64] = pack2(a1.w, a1.w);
        Bs[buf][lc + 0][lr] = b0.x; Bs[buf][lc + 1][lr] = b0.y;
        Bs[buf][lc + 2][lr] = b0.z; Bs[buf][lc + 3][lr] = b0.w;
        Bs[buf][lc + 0][lr + 64] = b1.x; Bs[buf][lc + 1][lr + 64] = b1.y;
        Bs[buf][lc + 2][lr + 64] = b1.z; Bs[buf][lc + 3][lr + 64] = b1.w;
    };
    auto cmp = [&](int buf) {
#pragma unroll
        for (int k = 0; k < 16; k++) {
            const ulonglong2* ap = (const ulonglong2*)&As2[buf][k][ty * 8];
            ulonglong2 aA = ap[0], aB = ap[1], aC = ap[2], aD = ap[3];
            const ulonglong2* bp = (const ulonglong2*)&Bs[buf][k][tx * 8];
            ulonglong2 bA = bp[0], bB = bp[1];
            ull av[8] = {aA.x, aA.y, aB.x, aB.y, aC.x, aC.y, aD.x, aD.y};
            ull bv[4] = {bA.x, bA.y, bB.x, bB.y};
#pragma unroll
            for (int i = 0; i < 8; i++)
#pragma unroll
                for (int j = 0; j < 4; j++)
                    acc[i][j] = ffma2(av[i], bv[j], acc[i][j]);
        }
    };

    {
        float4 a0, a1, b0, b1;
        ldTile(0, a0, a1, b0, b1);
        stTile(0, a0, a1, b0, b1);
    }
    int cur = 0;
#pragma unroll 1
    for (int t = 0; t < NT - 1; t++) {
        __syncthreads();
        float4 a0, a1, b0, b1;
        ldTile((t + 1) * 16, a0, a1, b0, b1);   // prefetch next tile (latency hidden by cmp)
        cmp(cur);
        stTile(cur ^ 1, a0, a1, b0, b1);
        cur ^= 1;
    }
    __syncthreads();
    cmp(cur);

#pragma unroll
    for (int i = 0; i < 8; i++) {
        int m = m0 + ty * 8 + i;
#pragma unroll
        for (int j = 0; j < 4; j++) {
            int n = n0 + tx * 8 + 2 * j;
            float2 v = unpack2(acc[i][j]);
            if (MODE == 0) {
                float2 o;
                o.x = v.x + __ldg(bias + n);
                o.y = v.y + __ldg(bias + n + 1);
                *(float2*)(C + (size_t)m * LDC + n) = o;
            } else {
                float2 fov = *(const float2*)(fo + (size_t)m * 256 + n);
                float2 fsv = *(const float2*)(fs + (size_t)m * 256 + n);
                float s0 = sigm(v.x + __ldg(bias + n));
                float s1 = sigm(v.y + __ldg(bias + n + 1));
                float2 o;
                o.x = s0 * fov.x + (1.f - s0) * fsv.x;
                o.y = s1 * fov.y + (1.f - s1) * fsv.y;
                *(float2*)(C + (size_t)m * LDC + n) = o;
            }
        }
    }
}

// ---------------- BiLSTM recurrence (2-CTA cluster per seq-dir, merged word+sent) ----------------
// grid.x = (64 + 1024)*2 CTAs, cluster (2,1,1). cidg = blockIdx.x/2.
// cidg <  64 : word  (L=1024, pre=pw*, W=Whh*, out=fo)
// cidg >= 64 : sent  (L=64,   pre=ps*, W=sWhh*, out=fs)
// CTA rank r owns hidden units [r*64, r*64+64); 256 threads own gate rows
// q*128 + r*64 + u, weights in registers. Double-buffered h, mbarrier count 512
// (256 local + 256 remote release). Last step: no barrier traffic; trailing
// cluster.sync prevents in-flight remote SMEM access to an exited CTA.
__global__ __launch_bounds__(256, 1)
void lstm_k(const float* __restrict__ pwf, const float* __restrict__ pwb,
            const float* __restrict__ Wf,  const float* __restrict__ Wb,
            float* __restrict__ fo,
            const float* __restrict__ psf, const float* __restrict__ psb,
            const float* __restrict__ sWf, const float* __restrict__ sWb,
            float* __restrict__ fs)
{
    __shared__ __align__(16) float h_sh[2][128];
    __shared__ float gacc[256];
    __shared__ __align__(8) ull bars[2];
    const int t = threadIdx.x;
    const int cidg = blockIdx.x >> 1;
    const uint32_t r = ctarank();

    const float *pre, *Whh; float* outb; int L, dir, seq;
    if (cidg < 64) {
        dir = cidg & 1; seq = cidg >> 1;
        pre = dir ? pwb : pwf; Whh = dir ? Wb : Wf; outb = fo; L = 1024;
    } else {
        int c = cidg - 64;
        dir = c & 1; seq = c >> 1;
        pre = dir ? psb : psf; Whh = dir ? sWb : sWf; outb = fs; L = 64;
    }
    const int q = t >> 6, u = t & 63;
    const int grow = q * 128 + (int)r * 64 + u;

    ull w2[64];
    {
        const ulonglong2* wr = (const ulonglong2*)(Whh + (size_t)grow * 128);
#pragma unroll
        for (int i = 0; i < 32; i++) { ulonglong2 v = wr[i]; w2[2 * i] = v.x; w2[2 * i + 1] = v.y; }
    }
    if (t < 128) { h_sh[0][t] = 0.f; h_sh[1][t] = 0.f; }
    uint32_t bar0 = smem_u32(&bars[0]), bar1 = smem_u32(&bars[1]);
    if (t == 0) { mbar_init(bar0, 512); mbar_init(bar1, 512); }
    __syncthreads();
    cluster_sync_();
    const uint32_t peer = r ^ 1u;
    const uint32_t rbar0 = mapa_u32(bar0, peer), rbar1 = mapa_u32(bar1, peer);
    const uint32_t hb0 = smem_u32(&h_sh[0][0]), hb1 = smem_u32(&h_sh[1][0]);
    const size_t seqbase = (size_t)seq * L;

    int ph0 = 0, ph1 = 0;
    float c = 0.f;
    float pv0 = __ldg(pre + (seqbase + (dir ? (L - 1) : 0)) * 512 + grow);
    float pv1 = (L > 1) ? __ldg(pre + (seqbase + (dir ? (L - 2) : 1)) * 512 + grow) : 0.f;

    for (int s = 0; s < L; s++) {
        int b = s & 1;
        if (s > 0) {
            if (b) { mbar_wait(bar1, ph1); ph1 ^= 1; }
            else   { mbar_wait(bar0, ph0); ph0 ^= 1; }
        }
        const ull* h2 = (const ull*)h_sh[b];
        ull a2 = 0ULL, a2b = 0ULL;
#pragma unroll
        for (int k = 0; k < 32; k++) {
            a2  = ffma2(w2[2 * k],     h2[2 * k],     a2);
            a2b = ffma2(w2[2 * k + 1], h2[2 * k + 1], a2b);
        }
        float2 av = unpack2(a2);
        float2 bv = unpack2(a2b);
        float acc = pv0 + (av.x + av.y) + (bv.x + bv.y);
        pv0 = pv1;
        int s2 = s + 2;
        pv1 = (s2 < L) ? __ldg(pre + (seqbase + (dir ? (L - 1 - s2) : s2)) * 512 + grow) : 0.f;
        gacc[t] = acc;
        __syncthreads();
        int nb = b ^ 1;
        bool last = (s == L - 1);
        if (t < 64) {
            float gi = gacc[t], gf = gacc[64 + t], gg = gacc[128 + t], go = gacc[192 + t];
            c = sigm(gf) * c + sigm(gi) * tanh_fast(gg);
            float h = sigm(go) * tanh_fast(c);
            int j = (int)r * 64 + t;
            int tp = dir ? (L - 1 - s) : s;
            outb[(seqbase + tp) * 256 + dir * 128 + j] = h;
            if (!last) {
                h_sh[nb][j] = h;
                st_cluster_f32(mapa_u32((nb ? hb1 : hb0) + 4u * j, peer), h);
            }
        }
        if (!last) {
            mbar_arrive_local(nb ? bar1 : bar0);
            mbar_arrive_rel_cluster(nb ? rbar1 : rbar0);
        }
    }
    cluster_sync_();
}

extern "C" void kernel_launch(void* const* d_in, const int* in_sizes, int n_in,
                              void* d_out, int out_size)
{
    (void)in_sizes; (void)out_size;
    const int off = (n_in >= 18) ? 1 : 0;   // skip seq_len scalar if present
    const int*   widx   = (const int*)d_in[0];
    const int*   sidx   = (const int*)d_in[1];
    const float* E      = (const float*)d_in[2 + off];
    const float* Wih_f  = (const float*)d_in[3 + off];
    const float* Whh_f  = (const float*)d_in[4 + off];
    const float* b_f    = (const float*)d_in[5 + off];
    const float* Wih_b  = (const float*)d_in[6 + off];
    const float* Whh_b  = (const float*)d_in[7 + off];
    const float* b_b    = (const float*)d_in[8 + off];
    const float* sWih_f = (const float*)d_in[9 + off];
    const float* sWhh_f = (const float*)d_in[10 + off];
    const float* sb_f   = (const float*)d_in[11 + off];
    const float* sWih_b = (const float*)d_in[12 + off];
    const float* sWhh_b = (const float*)d_in[13 + off];
    const float* sb_b   = (const float*)d_in[14 + off];
    const float* gW     = (const float*)d_in[15 + off];
    const float* gb     = (const float*)d_in[16 + off];
    float* out = (float*)d_out;

    float *pwf, *pwb, *psf, *psb, *fo, *fs;
    cudaGetSymbolAddress((void**)&pwf, g_pre_wf);
    cudaGetSymbolAddress((void**)&pwb, g_pre_wb);
    cudaGetSymbolAddress((void**)&psf, g_pre_sf);
    cudaGetSymbolAddress((void**)&psb, g_pre_sb);
    cudaGetSymbolAddress((void**)&fo, g_fo);
    cudaGetSymbolAddress((void**)&fs, g_fs);

    dim3 blk(256, 1, 1);
    dim3 gpre(MTOK / 128, 4, 1);
    // 4 pre-activation GEMMs (gather-fused embedding), double-buffered
    gemm_k<0, 768><<<gpre, blk>>>(widx, E, Wih_f, b_f, pwf, nullptr, nullptr);
    gemm_k<0, 768><<<gpre, blk>>>(widx, E, Wih_b, b_b, pwb, nullptr, nullptr);
    gemm_k<0, 768><<<gpre, blk>>>(sidx, E, sWih_f, sb_f, psf, nullptr, nullptr);
    gemm_k<0, 768><<<gpre, blk>>>(sidx, E, sWih_b, sb_b, psb, nullptr, nullptr);

    // merged BiLSTM: word (64 cids, L=1024) + sent (1024 cids, L=64) in one grid
    {
        cudaLaunchConfig_t cfg = {};
        cfg.gridDim = dim3((64 + 1024) * 2, 1, 1);
        cfg.blockDim = dim3(256, 1, 1);
        cfg.dynamicSmemBytes = 0;
        cfg.stream = 0;
        cudaLaunchAttribute attr[1];
        attr[0].id = cudaLaunchAttributeClusterDimension;
        attr[0].val.clusterDim.x = 2; attr[0].val.clusterDim.y = 1; attr[0].val.clusterDim.z = 1;
        cfg.attrs = attr; cfg.numAttrs = 1;
        cudaLaunchKernelEx(&cfg, lstm_k, (const float*)pwf, (const float*)pwb, Whh_f, Whh_b, fo,
                           (const float*)psf, (const float*)psb, sWhh_f, sWhh_b, fs);
    }

    // gate GEMM + blend
    dim3 ggate(MTOK / 128, 2, 1);
    gemm_k<1, 512><<<ggate, blk>>>(nullptr, nullptr, gW, gb, out, fo, fs);
}

// round 11
// speedup vs baseline: 1.4964x; 1.4338x over previous
#include <cuda_runtime.h>
#include <cstdint>
#include <math.h>

typedef unsigned long long ull;

#define MTOK 32768

// ---------------- static scratch ----------------
__device__ float g_pre_wf[MTOK * 512];
__device__ float g_pre_wb[MTOK * 512];
__device__ float g_pre_sf[MTOK * 512];
__device__ float g_pre_sb[MTOK * 512];
__device__ float g_fo[MTOK * 256];
__device__ float g_fs[MTOK * 256];

// ---------------- helpers ----------------
__device__ __forceinline__ ull ffma2(ull a, ull b, ull c) {
    ull d; asm("fma.rn.f32x2 %0,%1,%2,%3;" : "=l"(d) : "l"(a), "l"(b), "l"(c)); return d;
}
__device__ __forceinline__ ull pack2(float x, float y) {
    ull r; asm("mov.b64 %0,{%1,%2};" : "=l"(r) : "f"(x), "f"(y)); return r;
}
__device__ __forceinline__ float2 unpack2(ull v) {
    float2 r; asm("mov.b64 {%0,%1},%2;" : "=f"(r.x), "=f"(r.y) : "l"(v)); return r;
}
__device__ __forceinline__ uint32_t smem_u32(const void* p) {
    uint32_t a;
    asm("{ .reg .u64 t; cvta.to.shared.u64 t, %1; cvt.u32.u64 %0, t; }" : "=r"(a) : "l"(p));
    return a;
}
__device__ __forceinline__ uint32_t ctarank() {
    uint32_t r; asm("mov.u32 %0, %%cluster_ctarank;" : "=r"(r)); return r;
}
__device__ __forceinline__ uint32_t mapa_u32(uint32_t addr, uint32_t rank) {
    uint32_t r; asm("mapa.shared::cluster.u32 %0, %1, %2;" : "=r"(r) : "r"(addr), "r"(rank)); return r;
}
__device__ __forceinline__ void mbar_init(uint32_t a, uint32_t cnt) {
    asm volatile("mbarrier.init.shared.b64 [%0], %1;" :: "r"(a), "r"(cnt) : "memory");
}
__device__ __forceinline__ void st_cluster_f32(uint32_t a, float v) {
    asm volatile("st.shared::cluster.f32 [%0], %1;" :: "r"(a), "f"(v) : "memory");
}
__device__ __forceinline__ void mbar_arrive_local(uint32_t a) {
    asm volatile("mbarrier.arrive.shared.b64 _, [%0];" :: "r"(a) : "memory");
}
__device__ __forceinline__ void mbar_arrive_rel_cluster(uint32_t a) {
    asm volatile("mbarrier.arrive.release.cluster.shared::cluster.b64 _, [%0];" :: "r"(a) : "memory");
}
__device__ __forceinline__ void mbar_wait(uint32_t a, uint32_t parity) {
    asm volatile(
        "{\n\t.reg .pred P;\n\t"
        "WL_%=:\n\t"
        "mbarrier.try_wait.parity.acquire.cluster.shared::cta.b64 P, [%0], %1, 0x989680;\n\t"
        "@P bra.uni WD_%=;\n\t"
        "bra.uni WL_%=;\n\t"
        "WD_%=:\n\t}"
        :: "r"(a), "r"(parity) : "memory");
}
__device__ __forceinline__ void cluster_sync_() {
    asm volatile("barrier.cluster.arrive.aligned;" ::: "memory");
    asm volatile("barrier.cluster.wait.aligned;" ::: "memory");
}
__device__ __forceinline__ float sigm(float x) {
    return __fdividef(1.f, 1.f + __expf(-x));
}
// overflow-safe fast tanh
__device__ __forceinline__ float tanh_fast(float x) {
    float ax = fabsf(x);
    float e = __expf(-2.f * ax);
    float t = __fdividef(1.f - e, 1.f + e);
    return copysignf(t, x);
}

struct PreArgs {
    const int*   idx[4];
    const float* W[4];
    const float* bias[4];
    float*       C[4];
};

// ---------------- GEMM (m-pair accumulators, low smem traffic) ----------------
// MODE 0: C[m][n] = sum_k A[idx[m]][k]*W[n][k] + bias[n]; blockIdx.z selects gemm.
// MODE 1: A row = concat(fo[m], fs[m]) (KC=512); gate epilogue to out (ldc=256).
// smem layout: As/Bs [k][x] (x padded to 132); A read as natural (m,m+1) u64
// pairs (broadcast), B read as float4 (16B stride, 2-way) then duplicated (b,b)
// via mov.b64. 32 FFMA2 per k per thread, ~7 smem wavefronts/warp/k.
template <int MODE, int KC>
__global__ __launch_bounds__(256, 2)
void gemm_k(PreArgs pre, const float* __restrict__ E,
            const float* __restrict__ gW, const float* __restrict__ gb,
            float* __restrict__ out,
            const float* __restrict__ fo, const float* __restrict__ fs)
{
    __shared__ __align__(16) float As[2][16][132];
    __shared__ __align__(16) float Bs[2][16][132];
    const int tid = threadIdx.x;
    const int m0 = blockIdx.x * 128, n0 = blockIdx.y * 128;
    const int lr = tid >> 2, lc = (tid & 3) << 2;
    const int tx = tid & 15, ty = tid >> 4;
    constexpr int NT = KC / 16;

    const int g = (MODE == 0) ? (int)blockIdx.z : 0;
    const float* Wsel    = (MODE == 0) ? pre.W[g]    : gW;
    const float* biassel = (MODE == 0) ? pre.bias[g] : gb;
    float*       Csel    = (MODE == 0) ? pre.C[g]    : out;

    const float *a0p = nullptr, *a1p = nullptr;
    if (MODE == 0) {
        const int* idx = pre.idx[g];
        a0p = E + (size_t)__ldg(idx + m0 + lr) * KC + lc;
        a1p = E + (size_t)__ldg(idx + m0 + lr + 64) * KC + lc;
    }
    const float* b0p = Wsel + (size_t)(n0 + lr) * KC + lc;
    const float* b1p = Wsel + (size_t)(n0 + lr + 64) * KC + lc;

    ull acc[4][8];
#pragma unroll
    for (int i = 0; i < 4; i++)
#pragma unroll
        for (int j = 0; j < 8; j++) acc[i][j] = 0ULL;

    auto ldTile = [&](int k0, float4& a0, float4& a1, float4& b0, float4& b1) {
        if (MODE == 0) {
            a0 = *(const float4*)(a0p + k0);
            a1 = *(const float4*)(a1p + k0);
        } else {
            const float* base = (k0 < 256) ? fo : fs;
            int kk = (k0 < 256) ? k0 : (k0 - 256);
            a0 = *(const float4*)(base + (size_t)(m0 + lr) * 256 + kk + lc);
            a1 = *(const float4*)(base + (size_t)(m0 + lr + 64) * 256 + kk + lc);
        }
        b0 = *(const float4*)(b0p + k0);
        b1 = *(const float4*)(b1p + k0);
    };
    auto stTile = [&](int buf, const float4& a0, const float4& a1,
                      const float4& b0, const float4& b1) {
        As[buf][lc + 0][lr] = a0.x; As[buf][lc + 1][lr] = a0.y;
        As[buf][lc + 2][lr] = a0.z; As[buf][lc + 3][lr] = a0.w;
        As[buf][lc + 0][lr + 64] = a1.x; As[buf][lc + 1][lr + 64] = a1.y;
        As[buf][lc + 2][lr + 64] = a1.z; As[buf][lc + 3][lr + 64] = a1.w;
        Bs[buf][lc + 0][lr] = b0.x; Bs[buf][lc + 1][lr] = b0.y;
        Bs[buf][lc + 2][lr] = b0.z; Bs[buf][lc + 3][lr] = b0.w;
        Bs[buf][lc + 0][lr + 64] = b1.x; Bs[buf][lc + 1][lr + 64] = b1.y;
        Bs[buf][lc + 2][lr + 64] = b1.z; Bs[buf][lc + 3][lr + 64] = b1.w;
    };
    auto cmp = [&](int buf) {
#pragma unroll
        for (int k = 0; k < 16; k++) {
            const ulonglong2* ap = (const ulonglong2*)&As[buf][k][ty * 8];
            ulonglong2 aq0 = ap[0], aq1 = ap[1];
            ull am[4] = {aq0.x, aq0.y, aq1.x, aq1.y};
            float4 bf0 = *(const float4*)&Bs[buf][k][tx * 4];
            float4 bf1 = *(const float4*)&Bs[buf][k][64 + tx * 4];
            ull bd[8] = {pack2(bf0.x, bf0.x), pack2(bf0.y, bf0.y),
                         pack2(bf0.z, bf0.z), pack2(bf0.w, bf0.w),
                         pack2(bf1.x, bf1.x), pack2(bf1.y, bf1.y),
                         pack2(bf1.z, bf1.z), pack2(bf1.w, bf1.w)};
#pragma unroll
            for (int i = 0; i < 4; i++)
#pragma unroll
                for (int j = 0; j < 8; j++)
                    acc[i][j] = ffma2(am[i], bd[j], acc[i][j]);
        }
    };

    {
        float4 a0, a1, b0, b1;
        ldTile(0, a0, a1, b0, b1);
        stTile(0, a0, a1, b0, b1);
    }
    int cur = 0;
#pragma unroll 1
    for (int t = 0; t < NT - 1; t++) {
        __syncthreads();
        float4 a0, a1, b0, b1;
        ldTile((t + 1) * 16, a0, a1, b0, b1);
        cmp(cur);
        stTile(cur ^ 1, a0, a1, b0, b1);
        cur ^= 1;
    }
    __syncthreads();
    cmp(cur);

    // epilogue: acc[p][j] = (row m0+ty*8+2p, row +1) at n = n0 + h*64 + 4tx + (j%4)
#pragma unroll
    for (int p = 0; p < 4; p++) {
        int mrow = m0 + ty * 8 + 2 * p;
#pragma unroll
        for (int h = 0; h < 2; h++) {
            int n = n0 + h * 64 + tx * 4;
            int jb = h * 4;
            float2 v0 = unpack2(acc[p][jb + 0]);
            float2 v1 = unpack2(acc[p][jb + 1]);
            float2 v2 = unpack2(acc[p][jb + 2]);
            float2 v3 = unpack2(acc[p][jb + 3]);
            float4 bv = *(const float4*)(biassel + n);
            if (MODE == 0) {
                float4 o0 = {v0.x + bv.x, v1.x + bv.y, v2.x + bv.z, v3.x + bv.w};
                float4 o1 = {v0.y + bv.x, v1.y + bv.y, v2.y + bv.z, v3.y + bv.w};
                *(float4*)(Csel + (size_t)mrow * 512 + n) = o0;
                *(float4*)(Csel + (size_t)(mrow + 1) * 512 + n) = o1;
            } else {
                float4 fo0 = *(const float4*)(fo + (size_t)mrow * 256 + n);
                float4 fs0 = *(const float4*)(fs + (size_t)mrow * 256 + n);
                float4 fo1 = *(const float4*)(fo + (size_t)(mrow + 1) * 256 + n);
                float4 fs1 = *(const float4*)(fs + (size_t)(mrow + 1) * 256 + n);
                float s; float4 o0, o1;
                s = sigm(v0.x + bv.x); o0.x = s * fo0.x + (1.f - s) * fs0.x;
                s = sigm(v1.x + bv.y); o0.y = s * fo0.y + (1.f - s) * fs0.y;
                s = sigm(v2.x + bv.z); o0.z = s * fo0.z + (1.f - s) * fs0.z;
                s = sigm(v3.x + bv.w); o0.w = s * fo0.w + (1.f - s) * fs0.w;
                s = sigm(v0.y + bv.x); o1.x = s * fo1.x + (1.f - s) * fs1.x;
                s = sigm(v1.y + bv.y); o1.y = s * fo1.y + (1.f - s) * fs1.y;
                s = sigm(v2.y + bv.z); o1.z = s * fo1.z + (1.f - s) * fs1.z;
                s = sigm(v3.y + bv.w); o1.w = s * fo1.w + (1.f - s) * fs1.w;
                *(float4*)(Csel + (size_t)mrow * 256 + n) = o0;
                *(float4*)(Csel + (size_t)(mrow + 1) * 256 + n) = o1;
            }
        }
    }
}

// ---------------- BiLSTM recurrence (2-CTA cluster per seq-dir, merged word+sent) ----------------
// cidg <  64 : word (L=1024); cidg >= 64 : sent (L=64).
// 4 independent FFMA2 chains (dep depth 16); gate nonlinearities applied
// pre-barrier by the owning thread; post-sync path: 2 FMA + 1 tanh.
__global__ __launch_bounds__(256, 1)
void lstm_k(const float* __restrict__ pwf, const float* __restrict__ pwb,
            const float* __restrict__ Wf,  const float* __restrict__ Wb,
            float* __restrict__ fo,
            const float* __restrict__ psf, const float* __restrict__ psb,
            const float* __restrict__ sWf, const float* __restrict__ sWb,
            float* __restrict__ fs)
{
    __shared__ __align__(16) float h_sh[2][128];
    __shared__ float gacc[256];
    __shared__ __align__(8) ull bars[2];
    const int t = threadIdx.x;
    const int cidg = blockIdx.x >> 1;
    const uint32_t r = ctarank();

    const float *pre, *Whh; float* outb; int L, dir, seq;
    if (cidg < 64) {
        dir = cidg & 1; seq = cidg >> 1;
        pre = dir ? pwb : pwf; Whh = dir ? Wb : Wf; outb = fo; L = 1024;
    } else {
        int c = cidg - 64;
        dir = c & 1; seq = c >> 1;
        pre = dir ? psb : psf; Whh = dir ? sWb : sWf; outb = fs; L = 64;
    }
    const int q = t >> 6, u = t & 63;
    const int grow = q * 128 + (int)r * 64 + u;

    ull w2[64];
    {
        const ulonglong2* wr = (const ulonglong2*)(Whh + (size_t)grow * 128);
#pragma unroll
        for (int i = 0; i < 32; i++) { ulonglong2 v = wr[i]; w2[2 * i] = v.x; w2[2 * i + 1] = v.y; }
    }
    if (t < 128) { h_sh[0][t] = 0.f; h_sh[1][t] = 0.f; }
    uint32_t bar0 = smem_u32(&bars[0]), bar1 = smem_u32(&bars[1]);
    if (t == 0) { mbar_init(bar0, 512); mbar_init(bar1, 512); }
    __syncthreads();
    cluster_sync_();
    const uint32_t peer = r ^ 1u;
    const uint32_t rbar0 = mapa_u32(bar0, peer), rbar1 = mapa_u32(bar1, peer);
    const uint32_t hb0 = smem_u32(&h_sh[0][0]), hb1 = smem_u32(&h_sh[1][0]);
    const size_t seqbase = (size_t)seq * L;

    int ph0 = 0, ph1 = 0;
    float c = 0.f;
    float pv0 = __ldg(pre + (seqbase + (dir ? (L - 1) : 0)) * 512 + grow);
    float pv1 = (L > 1) ? __ldg(pre + (seqbase + (dir ? (L - 2) : 1)) * 512 + grow) : 0.f;

    for (int s = 0; s < L; s++) {
        int b = s & 1;
        if (s > 0) {
            if (b) { mbar_wait(bar1, ph1); ph1 ^= 1; }
            else   { mbar_wait(bar0, ph0); ph0 ^= 1; }
        }
        const ull* h2 = (const ull*)h_sh[b];
        ull c0 = 0ULL, c1 = 0ULL, c2 = 0ULL, c3 = 0ULL;
#pragma unroll
        for (int k = 0; k < 16; k++) {
            c0 = ffma2(w2[4 * k + 0], h2[4 * k + 0], c0);
            c1 = ffma2(w2[4 * k + 1], h2[4 * k + 1], c1);
            c2 = ffma2(w2[4 * k + 2], h2[4 * k + 2], c2);
            c3 = ffma2(w2[4 * k + 3], h2[4 * k + 3], c3);
        }
        float2 s0 = unpack2(c0), s1 = unpack2(c1), s2 = unpack2(c2), s3 = unpack2(c3);
        float acc = pv0 + ((s0.x + s0.y) + (s1.x + s1.y)) + ((s2.x + s2.y) + (s3.x + s3.y));
        pv0 = pv1;
        int sp2 = s + 2;
        pv1 = (sp2 < L) ? __ldg(pre + (seqbase + (dir ? (L - 1 - sp2) : sp2)) * 512 + grow) : 0.f;
        // apply own gate's nonlinearity pre-barrier: i,f,o -> sigmoid; g -> tanh
        gacc[t] = (q == 2) ? tanh_fast(acc) : sigm(acc);
        __syncthreads();
        int nb = b ^ 1;
        bool last = (s == L - 1);
        if (t < 64) {
            float gi = gacc[t], gf = gacc[64 + t], gg = gacc[128 + t], go = gacc[192 + t];
            c = gf * c + gi * gg;
            float h = go * tanh_fast(c);
            int j = (int)r * 64 + t;
            int tp = dir ? (L - 1 - s) : s;
            outb[(seqbase + tp) * 256 + dir * 128 + j] = h;
            if (!last) {
                h_sh[nb][j] = h;
                st_cluster_f32(mapa_u32((nb ? hb1 : hb0) + 4u * j, peer), h);
            }
        }
        if (!last) {
            mbar_arrive_local(nb ? bar1 : bar0);
            mbar_arrive_rel_cluster(nb ? rbar1 : rbar0);
        }
    }
    cluster_sync_();
}

extern "C" void kernel_launch(void* const* d_in, const int* in_sizes, int n_in,
                              void* d_out, int out_size)
{
    (void)in_sizes; (void)out_size;
    const int off = (n_in >= 18) ? 1 : 0;   // skip seq_len scalar if present
    const int*   widx   = (const int*)d_in[0];
    const int*   sidx   = (const int*)d_in[1];
    const float* E      = (const float*)d_in[2 + off];
    const float* Wih_f  = (const float*)d_in[3 + off];
    const float* Whh_f  = (const float*)d_in[4 + off];
    const float* b_f    = (const float*)d_in[5 + off];
    const float* Wih_b  = (const float*)d_in[6 + off];
    const float* Whh_b  = (const float*)d_in[7 + off];
    const float* b_b    = (const float*)d_in[8 + off];
    const float* sWih_f = (const float*)d_in[9 + off];
    const float* sWhh_f = (const float*)d_in[10 + off];
    const float* sb_f   = (const float*)d_in[11 + off];
    const float* sWih_b = (const float*)d_in[12 + off];
    const float* sWhh_b = (const float*)d_in[13 + off];
    const float* sb_b   = (const float*)d_in[14 + off];
    const float* gW     = (const float*)d_in[15 + off];
    const float* gb     = (const float*)d_in[16 + off];
    float* out = (float*)d_out;

    float *pwf, *pwb, *psf, *psb, *fo, *fs;
    cudaGetSymbolAddress((void**)&pwf, g_pre_wf);
    cudaGetSymbolAddress((void**)&pwb, g_pre_wb);
    cudaGetSymbolAddress((void**)&psf, g_pre_sf);
    cudaGetSymbolAddress((void**)&psb, g_pre_sb);
    cudaGetSymbolAddress((void**)&fo, g_fo);
    cudaGetSymbolAddress((void**)&fs, g_fs);

    dim3 blk(256, 1, 1);

    // 4 pre-activation GEMMs merged into one launch (blockIdx.z selects gemm)
    PreArgs pa;
    pa.idx[0] = widx; pa.idx[1] = widx; pa.idx[2] = sidx; pa.idx[3] = sidx;
    pa.W[0] = Wih_f;  pa.W[1] = Wih_b;  pa.W[2] = sWih_f; pa.W[3] = sWih_b;
    pa.bias[0] = b_f; pa.bias[1] = b_b; pa.bias[2] = sb_f; pa.bias[3] = sb_b;
    pa.C[0] = pwf;    pa.C[1] = pwb;    pa.C[2] = psf;    pa.C[3] = psb;
    dim3 gpre(MTOK / 128, 4, 4);
    gemm_k<0, 768><<<gpre, blk>>>(pa, E, nullptr, nullptr, nullptr, nullptr, nullptr);

    // merged BiLSTM: word (64 cids, L=1024) + sent (1024 cids, L=64) in one grid
    {
        cudaLaunchConfig_t cfg = {};
        cfg.gridDim = dim3((64 + 1024) * 2, 1, 1);
        cfg.blockDim = dim3(256, 1, 1);
        cfg.dynamicSmemBytes = 0;
        cfg.stream = 0;
        cudaLaunchAttribute attr[1];
        attr[0].id = cudaLaunchAttributeClusterDimension;
        attr[0].val.clusterDim.x = 2; attr[0].val.clusterDim.y = 1; attr[0].val.clusterDim.z = 1;
        cfg.attrs = attr; cfg.numAttrs = 1;
        cudaLaunchKernelEx(&cfg, lstm_k, (const float*)pwf, (const float*)pwb, Whh_f, Whh_b, fo,
                           (const float*)psf, (const float*)psb, sWhh_f, sWhh_b, fs);
    }

    // gate GEMM + blend
    PreArgs dummy = {};
    dim3 ggate(MTOK / 128, 2, 1);
    gemm_k<1, 512><<<ggate, blk>>>(dummy, nullptr, gW, gb, out, fo, fs);
}

// round 13
// speedup vs baseline: 1.8125x; 1.2112x over previous
#include <cuda_runtime.h>
#include <cuda_bf16.h>
#include <cstdint>
#include <math.h>

typedef unsigned long long ull;
typedef unsigned short u16;

#define MTOK 32768
#define EROWS 30522
#define KDIM  768
#define EELEM (EROWS * KDIM)
#define WELEM (512 * KDIM)

// ---------------- static scratch ----------------
__device__ float g_pre_wf[MTOK * 512];
__device__ float g_pre_wb[MTOK * 512];
__device__ float g_pre_sf[MTOK * 512];
__device__ float g_pre_sb[MTOK * 512];
__device__ float g_fo[MTOK * 256];
__device__ float g_fs[MTOK * 256];
__device__ u16 g_Eh[EELEM];
__device__ u16 g_El[EELEM];
__device__ u16 g_Wh[4 * WELEM];
__device__ u16 g_Wl[4 * WELEM];

// ---------------- helpers ----------------
__device__ __forceinline__ ull ffma2(ull a, ull b, ull c) {
    ull d; asm("fma.rn.f32x2 %0,%1,%2,%3;" : "=l"(d) : "l"(a), "l"(b), "l"(c)); return d;
}
__device__ __forceinline__ ull pack2(float x, float y) {
    ull r; asm("mov.b64 %0,{%1,%2};" : "=l"(r) : "f"(x), "f"(y)); return r;
}
__device__ __forceinline__ float2 unpack2(ull v) {
    float2 r; asm("mov.b64 {%0,%1},%2;" : "=f"(r.x), "=f"(r.y) : "l"(v)); return r;
}
__device__ __forceinline__ uint32_t smem_u32(const void* p) {
    uint32_t a;
    asm("{ .reg .u64 t; cvta.to.shared.u64 t, %1; cvt.u32.u64 %0, t; }" : "=r"(a) : "l"(p));
    return a;
}
__device__ __forceinline__ uint32_t ctarank() {
    uint32_t r; asm("mov.u32 %0, %%cluster_ctarank;" : "=r"(r)); return r;
}
__device__ __forceinline__ uint32_t mapa_u32(uint32_t addr, uint32_t rank) {
    uint32_t r; asm("mapa.shared::cluster.u32 %0, %1, %2;" : "=r"(r) : "r"(addr), "r"(rank)); return r;
}
__device__ __forceinline__ void mbar_init(uint32_t a, uint32_t cnt) {
    asm volatile("mbarrier.init.shared.b64 [%0], %1;" :: "r"(a), "r"(cnt) : "memory");
}
__device__ __forceinline__ void st_cluster_f32(uint32_t a, float v) {
    asm volatile("st.shared::cluster.f32 [%0], %1;" :: "r"(a), "f"(v) : "memory");
}
__device__ __forceinline__ void mbar_arrive_local(uint32_t a) {
    asm volatile("mbarrier.arrive.shared.b64 _, [%0];" :: "r"(a) : "memory");
}
__device__ __forceinline__ void mbar_arrive_rel_cluster(uint32_t a) {
    asm volatile("mbarrier.arrive.release.cluster.shared::cluster.b64 _, [%0];" :: "r"(a) : "memory");
}
__device__ __forceinline__ void mbar_wait(uint32_t a, uint32_t parity) {
    asm volatile(
        "{\n\t.reg .pred P;\n\t"
        "WL_%=:\n\t"
        "mbarrier.try_wait.parity.acquire.cluster.shared::cta.b64 P, [%0], %1, 0x989680;\n\t"
        "@P bra.uni WD_%=;\n\t"
        "bra.uni WL_%=;\n\t"
        "WD_%=:\n\t}"
        :: "r"(a), "r"(parity) : "memory");
}
__device__ __forceinline__ void cluster_sync_() {
    asm volatile("barrier.cluster.arrive.aligned;" ::: "memory");
    asm volatile("barrier.cluster.wait.aligned;" ::: "memory");
}
__device__ __forceinline__ float sigm(float x) {
    return __fdividef(1.f, 1.f + __expf(-x));
}
__device__ __forceinline__ float tanh_fast(float x) {
    float ax = fabsf(x);
    float e = __expf(-2.f * ax);
    float t = __fdividef(1.f - e, 1.f + e);
    return copysignf(t, x);
}

// ---- Ampere-class tensor primitives (no 'a'-suffix features) ----
__device__ __forceinline__ void ldsm_x4(uint32_t& r0, uint32_t& r1, uint32_t& r2, uint32_t& r3,
                                        uint32_t addr) {
    asm volatile("ldmatrix.sync.aligned.m8n8.x4.shared.b16 {%0,%1,%2,%3}, [%4];"
                 : "=r"(r0), "=r"(r1), "=r"(r2), "=r"(r3) : "r"(addr));
}
__device__ __forceinline__ void mma_bf16(float* d, const uint32_t* a, const uint32_t* b) {
    asm volatile("mma.sync.aligned.m16n8k16.row.col.f32.bf16.bf16.f32 "
                 "{%0,%1,%2,%3}, {%4,%5,%6,%7}, {%8,%9}, {%0,%1,%2,%3};"
                 : "+f"(d[0]), "+f"(d[1]), "+f"(d[2]), "+f"(d[3])
                 : "r"(a[0]), "r"(a[1]), "r"(a[2]), "r"(a[3]), "r"(b[0]), "r"(b[1]));
}
__device__ __forceinline__ void cp_async16(uint32_t dst, const void* src) {
    asm volatile("cp.async.cg.shared.global [%0], [%1], 16;" :: "r"(dst), "l"(src) : "memory");
}
__device__ __forceinline__ void cp_commit() { asm volatile("cp.async.commit_group;" ::: "memory"); }
__device__ __forceinline__ void cp_wait1() { asm volatile("cp.async.wait_group 1;" ::: "memory"); }

// ---------------- bf16 hi/lo split ----------------
__global__ void cvt_split_k(const float* __restrict__ x, u16* __restrict__ hi,
                            u16* __restrict__ lo, int n4)
{
    int i = blockIdx.x * blockDim.x + threadIdx.x;
    if (i >= n4) return;
    float4 v = __ldg((const float4*)x + i);
    __nv_bfloat16 h0 = __float2bfloat16(v.x), h1 = __float2bfloat16(v.y);
    __nv_bfloat16 h2 = __float2bfloat16(v.z), h3 = __float2bfloat16(v.w);
    __nv_bfloat16 l0 = __float2bfloat16(v.x - __bfloat162float(h0));
    __nv_bfloat16 l1 = __float2bfloat16(v.y - __bfloat162float(h1));
    __nv_bfloat16 l2 = __float2bfloat16(v.z - __bfloat162float(h2));
    __nv_bfloat16 l3 = __float2bfloat16(v.w - __bfloat162float(h3));
    ushort4 hv = {__bfloat16_as_ushort(h0), __bfloat16_as_ushort(h1),
                  __bfloat16_as_ushort(h2), __bfloat16_as_ushort(h3)};
    ushort4 lv = {__bfloat16_as_ushort(l0), __bfloat16_as_ushort(l1),
                  __bfloat16_as_ushort(l2), __bfloat16_as_ushort(l3)};
    *(ushort4*)(hi + 4 * i) = hv;
    *(ushort4*)(lo + 4 * i) = lv;
}

// ---------------- HMMA pre-activation GEMM ----------------
// C[m][n] = sum_k A[idx[m]][k]*W[n][k] + bias[n] via bf16 3-term split
// (Ah*Bh + Al*Bh + Ah*Bl; K_eff = 3*768, 36 chunks of 64).
// Tile 128x128, 8 warps (4x2), warp tile 32x64, SW128 smem, cp.async 2-stage.
struct TcArgs {
    const int*   idx[4];
    const float* bias[4];
    float*       C[4];
};

#define STG 32768
#define MG_SMEM (1024 + 2 * STG)

__device__ __forceinline__ uint32_t swaddr(uint32_t base, int row, int chunk) {
    uint32_t off = (uint32_t)(row * 128 + chunk * 16);
    return base + (off ^ ((off >> 3) & 0x70));
}

__global__ __launch_bounds__(256, 2)
void mma_gemm(TcArgs args, const u16* __restrict__ Eh, const u16* __restrict__ El,
              const u16* __restrict__ Wh, const u16* __restrict__ Wl)
{
    extern __shared__ char sm[];
    const int tid = threadIdx.x, lid = tid & 31, wid = tid >> 5;
    const int m0 = blockIdx.x * 128, n0 = blockIdx.y * 128, z = blockIdx.z;
    const u16* Whz = Wh + (size_t)z * WELEM;
    const u16* Wlz = Wl + (size_t)z * WELEM;
    int* idx_sm = (int*)sm;
    if (tid < 128) idx_sm[tid] = __ldg(args.idx[z] + m0 + tid);
    __syncthreads();
    const uint32_t smb = smem_u32(sm);
    const int wm = wid & 3, wn = wid >> 2;

    // per-thread cp.async coords: thread t -> tile row t>>1, 64B half (t&1)
    const int ldrow = tid >> 1, ldh = tid & 1;
    const size_t a_gr = (size_t)idx_sm[ldrow] * KDIM + ldh * 32;
    const size_t b_gr = (size_t)(n0 + ldrow) * KDIM + ldh * 32;
    uint32_t adst[4], bdst[4];
#pragma unroll
    for (int s = 0; s < 4; s++) {
        adst[s] = swaddr(smb + 1024, ldrow, ldh * 4 + s);
        bdst[s] = swaddr(smb + 1024 + 16384, ldrow, ldh * 4 + s);
    }

    float d[2][8][4];
#pragma unroll
    for (int i = 0; i < 2; i++)
#pragma unroll
        for (int j = 0; j < 8; j++)
#pragma unroll
            for (int k = 0; k < 4; k++) d[i][j][k] = 0.f;

    auto issue = [&](int c, int buf) {
        const int p = c / 12, kbase = (c % 12) * 64;
        const u16* As = (p == 1) ? El : Eh;
        const u16* Bs = (p == 2) ? Wlz : Whz;
        const u16* as = As + a_gr + kbase;
        const u16* bs = Bs + b_gr + kbase;
        const uint32_t bo = (uint32_t)(buf * STG);
#pragma unroll
        for (int s = 0; s < 4; s++) cp_async16(adst[s] + bo, as + 8 * s);
#pragma unroll
        for (int s = 0; s < 4; s++) cp_async16(bdst[s] + bo, bs + 8 * s);
    };

    // ldmatrix lane roles
    const int g8 = lid & 7, grp = lid >> 3;
    const int arow_off = g8 + ((grp & 1) << 3);   // A: g0/g2 rows+0-7, g1/g3 rows+8-15
    const int acol_sel = grp >> 1;                // A: chunk +0 for g0/g1, +1 for g2/g3
    const int brow_off = g8 + ((grp >> 1) << 3);  // B: g0/g1 rows+0-7, g2/g3 rows+8-15
    const int bcol_sel = grp & 1;                 // B: chunk +0 g0/g2, +1 g1/g3

    issue(0, 0); cp_commit();
    issue(1, 1); cp_commit();

#pragma unroll 1
    for (int c = 0; c < 36; c++) {
        const int buf = c & 1;
        cp_wait1();
        __syncthreads();
        const uint32_t abase = smb + 1024 + buf * STG;
        const uint32_t bbase = abase + 16384;
#pragma unroll
        for (int kt2 = 0; kt2 < 2; kt2++) {
            uint32_t a[2][2][4];
#pragma unroll
            for (int mt = 0; mt < 2; mt++)
#pragma unroll
                for (int kk = 0; kk < 2; kk++) {
                    int kt = 2 * kt2 + kk;
                    ldsm_x4(a[mt][kk][0], a[mt][kk][1], a[mt][kk][2], a[mt][kk][3],
                            swaddr(abase, wm * 32 + mt * 16 + arow_off, 2 * kt + acol_sel));
                }
#pragma unroll
            for (int nt = 0; nt < 4; nt++) {
                uint32_t b[2][4];
#pragma unroll
                for (int kk = 0; kk < 2; kk++) {
                    int kt = 2 * kt2 + kk;
                    ldsm_x4(b[kk][0], b[kk][1], b[kk][2], b[kk][3],
                            swaddr(bbase, wn * 64 + nt * 16 + brow_off, 2 * kt + bcol_sel));
                }
#pragma unroll
                for (int mt = 0; mt < 2; mt++)
#pragma unroll
                    for (int n8 = 0; n8 < 2; n8++)
#pragma unroll
                        for (int kk = 0; kk < 2; kk++)
                            mma_bf16(d[mt][nt * 2 + n8], a[mt][kk], &b[kk][n8 * 2]);
            }
        }
        __syncthreads();
        if (c + 2 < 36) issue(c + 2, buf);
        cp_commit();
    }

    // epilogue: frag (mt, f): rows m0+wm*32+mt*16+(lid>>2)(+8), cols n0+wn*64+f*8+2*(lid&3)
    const float* bias = args.bias[z];
    float* C = args.C[z];
#pragma unroll
    for (int mt = 0; mt < 2; mt++) {
        int r0 = m0 + wm * 32 + mt * 16 + (lid >> 2);
#pragma unroll
        for (int f = 0; f < 8; f++) {
            int n = n0 + wn * 64 + f * 8 + 2 * (lid & 3);
            float2 bv = *(const float2*)(bias + n);
            float2 o0 = {d[mt][f][0] + bv.x, d[mt][f][1] + bv.y};
            float2 o1 = {d[mt][f][2] + bv.x, d[mt][f][3] + bv.y};
            *(float2*)(C + (size_t)r0 * 512 + n) = o0;
            *(float2*)(C + (size_t)(r0 + 8) * 512 + n) = o1;
        }
    }
}

// ---------------- gate GEMM + blend (FFMA2, unchanged) ----------------
__global__ __launch_bounds__(256, 2)
void gate_k(const float* __restrict__ gW, const float* __restrict__ gb,
            float* __restrict__ out,
            const float* __restrict__ fo, const float* __restrict__ fs)
{
    __shared__ __align__(16) float As[2][16][132];
    __shared__ __align__(16) float Bs[2][16][132];
    const int tid = threadIdx.x;
    const int m0 = blockIdx.x * 128, n0 = blockIdx.y * 128;
    const int lr = tid >> 2, lc = (tid & 3) << 2;
    const int tx = tid & 15, ty = tid >> 4;
    constexpr int KC = 512, NT = KC / 16;

    const float* b0p = gW + (size_t)(n0 + lr) * KC + lc;
    const float* b1p = gW + (size_t)(n0 + lr + 64) * KC + lc;

    ull acc[4][8];
#pragma unroll
    for (int i = 0; i < 4; i++)
#pragma unroll
        for (int j = 0; j < 8; j++) acc[i][j] = 0ULL;

    auto ldTile = [&](int k0, float4& a0, float4& a1, float4& b0, float4& b1) {
        const float* base = (k0 < 256) ? fo : fs;
        int kk = (k0 < 256) ? k0 : (k0 - 256);
        a0 = *(const float4*)(base + (size_t)(m0 + lr) * 256 + kk + lc);
        a1 = *(const float4*)(base + (size_t)(m0 + lr + 64) * 256 + kk + lc);
        b0 = *(const float4*)(b0p + k0);
        b1 = *(const float4*)(b1p + k0);
    };
    auto stTile = [&](int buf, const float4& a0, const float4& a1,
                      const float4& b0, const float4& b1) {
        As[buf][lc + 0][lr] = a0.x; As[buf][lc + 1][lr] = a0.y;
        As[buf][lc + 2][lr] = a0.z; As[buf][lc + 3][lr] = a0.w;
        As[buf][lc + 0][lr + 64] = a1.x; As[buf][lc + 1][lr + 64] = a1.y;
        As[buf][lc + 2][lr + 64] = a1.z; As[buf][lc + 3][lr + 64] = a1.w;
        Bs[buf][lc + 0][lr] = b0.x; Bs[buf][lc + 1][lr] = b0.y;
        Bs[buf][lc + 2][lr] = b0.z; Bs[buf][lc + 3][lr] = b0.w;
        Bs[buf][lc + 0][lr + 64] = b1.x; Bs[buf][lc + 1][lr + 64] = b1.y;
        Bs[buf][lc + 2][lr + 64] = b1.z; Bs[buf][lc + 3][lr + 64] = b1.w;
    };
    auto cmp = [&](int buf) {
#pragma unroll
        for (int k = 0; k < 16; k++) {
            const ulonglong2* ap = (const ulonglong2*)&As[buf][k][ty * 8];
            ulonglong2 aq0 = ap[0], aq1 = ap[1];
            ull am[4] = {aq0.x, aq0.y, aq1.x, aq1.y};
            float4 bf0 = *(const float4*)&Bs[buf][k][tx * 4];
            float4 bf1 = *(const float4*)&Bs[buf][k][64 + tx * 4];
            ull bd[8] = {pack2(bf0.x, bf0.x), pack2(bf0.y, bf0.y),
                         pack2(bf0.z, bf0.z), pack2(bf0.w, bf0.w),
                         pack2(bf1.x, bf1.x), pack2(bf1.y, bf1.y),
                         pack2(bf1.z, bf1.z), pack2(bf1.w, bf1.w)};
#pragma unroll
            for (int i = 0; i < 4; i++)
#pragma unroll
                for (int j = 0; j < 8; j++)
                    acc[i][j] = ffma2(am[i], bd[j], acc[i][j]);
        }
    };

    {
        float4 a0, a1, b0, b1;
        ldTile(0, a0, a1, b0, b1);
        stTile(0, a0, a1, b0, b1);
    }
    int cur = 0;
#pragma unroll 1
    for (int t = 0; t < NT - 1; t++) {
        __syncthreads();
        float4 a0, a1, b0, b1;
        ldTile((t + 1) * 16, a0, a1, b0, b1);
        cmp(cur);
        stTile(cur ^ 1, a0, a1, b0, b1);
        cur ^= 1;
    }
    __syncthreads();
    cmp(cur);

#pragma unroll
    for (int p = 0; p < 4; p++) {
        int mrow = m0 + ty * 8 + 2 * p;
#pragma unroll
        for (int h = 0; h < 2; h++) {
            int n = n0 + h * 64 + tx * 4;
            int jb = h * 4;
            float2 v0 = unpack2(acc[p][jb + 0]);
            float2 v1 = unpack2(acc[p][jb + 1]);
            float2 v2 = unpack2(acc[p][jb + 2]);
            float2 v3 = unpack2(acc[p][jb + 3]);
            float4 bv = *(const float4*)(gb + n);
            float4 fo0 = *(const float4*)(fo + (size_t)mrow * 256 + n);
            float4 fs0 = *(const float4*)(fs + (size_t)mrow * 256 + n);
            float4 fo1 = *(const float4*)(fo + (size_t)(mrow + 1) * 256 + n);
            float4 fs1 = *(const float4*)(fs + (size_t)(mrow + 1) * 256 + n);
            float s; float4 o0, o1;
            s = sigm(v0.x + bv.x); o0.x = s * fo0.x + (1.f - s) * fs0.x;
            s = sigm(v1.x + bv.y); o0.y = s * fo0.y + (1.f - s) * fs0.y;
            s = sigm(v2.x + bv.z); o0.z = s * fo0.z + (1.f - s) * fs0.z;
            s = sigm(v3.x + bv.w); o0.w = s * fo0.w + (1.f - s) * fs0.w;
            s = sigm(v0.y + bv.x); o1.x = s * fo1.x + (1.f - s) * fs1.x;
            s = sigm(v1.y + bv.y); o1.y = s * fo1.y + (1.f - s) * fs1.y;
            s = sigm(v2.y + bv.z); o1.z = s * fo1.z + (1.f - s) * fs1.z;
            s = sigm(v3.y + bv.w); o1.w = s * fo1.w + (1.f - s) * fs1.w;
            *(float4*)(out + (size_t)mrow * 256 + n) = o0;
            *(float4*)(out + (size_t)(mrow + 1) * 256 + n) = o1;
        }
    }
}

// ---------------- BiLSTM recurrence (unchanged, proven) ----------------
__global__ __launch_bounds__(256, 1)
void lstm_k(const float* __restrict__ pwf, const float* __restrict__ pwb,
            const float* __restrict__ Wf,  const float* __restrict__ Wb,
            float* __restrict__ fo,
            const float* __restrict__ psf, const float* __restrict__ psb,
            const float* __restrict__ sWf, const float* __restrict__ sWb,
            float* __restrict__ fs)
{
    __shared__ __align__(16) float h_sh[2][128];
    __shared__ float gacc[256];
    __shared__ __align__(8) ull bars[2];
    const int t = threadIdx.x;
    const int cidg = blockIdx.x >> 1;
    const uint32_t r = ctarank();

    const float *pre, *Whh; float* outb; int L, dir, seq;
    if (cidg < 64) {
        dir = cidg & 1; seq = cidg >> 1;
        pre = dir ? pwb : pwf; Whh = dir ? Wb : Wf; outb = fo; L = 1024;
    } else {
        int c = cidg - 64;
        dir = c & 1; seq = c >> 1;
        pre = dir ? psb : psf; Whh = dir ? sWb : sWf; outb = fs; L = 64;
    }
    const int q = t >> 6, u = t & 63;
    const int grow = q * 128 + (int)r * 64 + u;

    ull w2[64];
    {
        const ulonglong2* wr = (const ulonglong2*)(Whh + (size_t)grow * 128);
#pragma unroll
        for (int i = 0; i < 32; i++) { ulonglong2 v = wr[i]; w2[2 * i] = v.x; w2[2 * i + 1] = v.y; }
    }
    if (t < 128) { h_sh[0][t] = 0.f; h_sh[1][t] = 0.f; }
    uint32_t bar0 = smem_u32(&bars[0]), bar1 = smem_u32(&bars[1]);
    if (t == 0) { mbar_init(bar0, 512); mbar_init(bar1, 512); }
    __syncthreads();
    cluster_sync_();
    const uint32_t peer = r ^ 1u;
    const uint32_t rbar0 = mapa_u32(bar0, peer), rbar1 = mapa_u32(bar1, peer);
    const uint32_t hb0 = smem_u32(&h_sh[0][0]), hb1 = smem_u32(&h_sh[1][0]);
    const size_t seqbase = (size_t)seq * L;

    int ph0 = 0, ph1 = 0;
    float c = 0.f;
    float pv0 = __ldg(pre + (seqbase + (dir ? (L - 1) : 0)) * 512 + grow);
    float pv1 = (L > 1) ? __ldg(pre + (seqbase + (dir ? (L - 2) : 1)) * 512 + grow) : 0.f;

    for (int s = 0; s < L; s++) {
        int b = s & 1;
        if (s > 0) {
            if (b) { mbar_wait(bar1, ph1); ph1 ^= 1; }
            else   { mbar_wait(bar0, ph0); ph0 ^= 1; }
        }
        const ull* h2 = (const ull*)h_sh[b];
        ull c0 = 0ULL, c1 = 0ULL, c2 = 0ULL, c3 = 0ULL;
#pragma unroll
        for (int k = 0; k < 16; k++) {
            c0 = ffma2(w2[4 * k + 0], h2[4 * k + 0], c0);
            c1 = ffma2(w2[4 * k + 1], h2[4 * k + 1], c1);
            c2 = ffma2(w2[4 * k + 2], h2[4 * k + 2], c2);
            c3 = ffma2(w2[4 * k + 3], h2[4 * k + 3], c3);
        }
        float2 s0 = unpack2(c0), s1 = unpack2(c1), s2 = unpack2(c2), s3 = unpack2(c3);
        float acc = pv0 + ((s0.x + s0.y) + (s1.x + s1.y)) + ((s2.x + s2.y) + (s3.x + s3.y));
        pv0 = pv1;
        int sp2 = s + 2;
        pv1 = (sp2 < L) ? __ldg(pre + (seqbase + (dir ? (L - 1 - sp2) : sp2)) * 512 + grow) : 0.f;
        gacc[t] = (q == 2) ? tanh_fast(acc) : sigm(acc);
        __syncthreads();
        int nb = b ^ 1;
        bool last = (s == L - 1);
        if (t < 64) {
            float gi = gacc[t], gf = gacc[64 + t], gg = gacc[128 + t], go = gacc[192 + t];
            c = gf * c + gi * gg;
            float h = go * tanh_fast(c);
            int j = (int)r * 64 + t;
            int tp = dir ? (L - 1 - s) : s;
            outb[(seqbase + tp) * 256 + dir * 128 + j] = h;
            if (!last) {
                h_sh[nb][j] = h;
                st_cluster_f32(mapa_u32((nb ? hb1 : hb0) + 4u * j, peer), h);
            }
        }
        if (!last) {
            mbar_arrive_local(nb ? bar1 : bar0);
            mbar_arrive_rel_cluster(nb ? rbar1 : rbar0);
        }
    }
    cluster_sync_();
}

extern "C" void kernel_launch(void* const* d_in, const int* in_sizes, int n_in,
                              void* d_out, int out_size)
{
    (void)in_sizes; (void)out_size;
    const int off = (n_in >= 18) ? 1 : 0;
    const int*   widx   = (const int*)d_in[0];
    const int*   sidx   = (const int*)d_in[1];
    const float* E      = (const float*)d_in[2 + off];
    const float* Wih_f  = (const float*)d_in[3 + off];
    const float* Whh_f  = (const float*)d_in[4 + off];
    const float* b_f    = (const float*)d_in[5 + off];
    const float* Wih_b  = (const float*)d_in[6 + off];
    const float* Whh_b  = (const float*)d_in[7 + off];
    const float* b_b    = (const float*)d_in[8 + off];
    const float* sWih_f = (const float*)d_in[9 + off];
    const float* sWhh_f = (const float*)d_in[10 + off];
    const float* sb_f   = (const float*)d_in[11 + off];
    const float* sWih_b = (const float*)d_in[12 + off];
    const float* sWhh_b = (const float*)d_in[13 + off];
    const float* sb_b   = (const float*)d_in[14 + off];
    const float* gW     = (const float*)d_in[15 + off];
    const float* gb     = (const float*)d_in[16 + off];
    float* out = (float*)d_out;

    float *pwf, *pwb, *psf, *psb, *fo, *fs;
    u16 *eh, *el, *wh, *wl;
    cudaGetSymbolAddress((void**)&pwf, g_pre_wf);
    cudaGetSymbolAddress((void**)&pwb, g_pre_wb);
    cudaGetSymbolAddress((void**)&psf, g_pre_sf);
    cudaGetSymbolAddress((void**)&psb, g_pre_sb);
    cudaGetSymbolAddress((void**)&fo, g_fo);
    cudaGetSymbolAddress((void**)&fs, g_fs);
    cudaGetSymbolAddress((void**)&eh, g_Eh);
    cudaGetSymbolAddress((void**)&el, g_El);
    cudaGetSymbolAddress((void**)&wh, g_Wh);
    cudaGetSymbolAddress((void**)&wl, g_Wl);

    // bf16 hi/lo splits
    const int n4E = EELEM / 4;
    cvt_split_k<<<(n4E + 255) / 256, 256>>>(E, eh, el, n4E);
    const int n4W = WELEM / 4;
    cvt_split_k<<<(n4W + 255) / 256, 256>>>(Wih_f,  wh + 0 * WELEM, wl + 0 * WELEM, n4W);
    cvt_split_k<<<(n4W + 255) / 256, 256>>>(Wih_b,  wh + 1 * WELEM, wl + 1 * WELEM, n4W);
    cvt_split_k<<<(n4W + 255) / 256, 256>>>(sWih_f, wh + 2 * WELEM, wl + 2 * WELEM, n4W);
    cvt_split_k<<<(n4W + 255) / 256, 256>>>(sWih_b, wh + 3 * WELEM, wl + 3 * WELEM, n4W);

    // 4 pre-activation GEMMs on HMMA tensor path
    TcArgs ta;
    ta.idx[0] = widx; ta.idx[1] = widx; ta.idx[2] = sidx; ta.idx[3] = sidx;
    ta.bias[0] = b_f; ta.bias[1] = b_b; ta.bias[2] = sb_f; ta.bias[3] = sb_b;
    ta.C[0] = pwf;    ta.C[1] = pwb;    ta.C[2] = psf;    ta.C[3] = psb;
    cudaFuncSetAttribute(mma_gemm, cudaFuncAttributeMaxDynamicSharedMemorySize, MG_SMEM);
    mma_gemm<<<dim3(MTOK / 128, 4, 4), 256, MG_SMEM>>>(ta, eh, el, wh, wl);

    // merged BiLSTM
    {
        cudaLaunchConfig_t cfg = {};
        cfg.gridDim = dim3((64 + 1024) * 2, 1, 1);
        cfg.blockDim = dim3(256, 1, 1);
        cfg.dynamicSmemBytes = 0;
        cfg.stream = 0;
        cudaLaunchAttribute attr[1];
        attr[0].id = cudaLaunchAttributeClusterDimension;
        attr[0].val.clusterDim.x = 2; attr[0].val.clusterDim.y = 1; attr[0].val.clusterDim.z = 1;
        cfg.attrs = attr; cfg.numAttrs = 1;
        cudaLaunchKernelEx(&cfg, lstm_k, (const float*)pwf, (const float*)pwb, Whh_f, Whh_b, fo,
                           (const float*)psf, (const float*)psb, sWhh_f, sWhh_b, fs);
    }

    // gate GEMM + blend
    dim3 ggate(MTOK / 128, 2, 1);
    gate_k<<<ggate, dim3(256, 1, 1)>>>(gW, gb, out, fo, fs);
}

// round 14
// speedup vs baseline: 1.8629x; 1.0278x over previous
#include <cuda_runtime.h>
#include <cuda_bf16.h>
#include <cstdint>
#include <math.h>

typedef unsigned long long ull;
typedef unsigned short u16;

#define MTOK 32768
#define EROWS 30522
#define KDIM  768
#define EELEM (EROWS * KDIM)
#define WELEM (512 * KDIM)

// ---------------- static scratch ----------------
__device__ float g_pre_wf[MTOK * 512];
__device__ float g_pre_wb[MTOK * 512];
__device__ float g_pre_sf[MTOK * 512];
__device__ float g_pre_sb[MTOK * 512];
__device__ float g_fo[MTOK * 256];
__device__ float g_fs[MTOK * 256];
__device__ u16 g_Eh[EELEM];
__device__ u16 g_El[EELEM];
__device__ u16 g_Wh[4 * WELEM];
__device__ u16 g_Wl[4 * WELEM];
__device__ u16 g_foh[MTOK * 256];
__device__ u16 g_fol[MTOK * 256];
__device__ u16 g_fsh[MTOK * 256];
__device__ u16 g_fsl[MTOK * 256];
__device__ u16 g_gWh[256 * 512];
__device__ u16 g_gWl[256 * 512];

// ---------------- helpers ----------------
__device__ __forceinline__ ull ffma2(ull a, ull b, ull c) {
    ull d; asm("fma.rn.f32x2 %0,%1,%2,%3;" : "=l"(d) : "l"(a), "l"(b), "l"(c)); return d;
}
__device__ __forceinline__ float2 unpack2(ull v) {
    float2 r; asm("mov.b64 {%0,%1},%2;" : "=f"(r.x), "=f"(r.y) : "l"(v)); return r;
}
__device__ __forceinline__ uint32_t smem_u32(const void* p) {
    uint32_t a;
    asm("{ .reg .u64 t; cvta.to.shared.u64 t, %1; cvt.u32.u64 %0, t; }" : "=r"(a) : "l"(p));
    return a;
}
__device__ __forceinline__ uint32_t ctarank() {
    uint32_t r; asm("mov.u32 %0, %%cluster_ctarank;" : "=r"(r)); return r;
}
__device__ __forceinline__ uint32_t mapa_u32(uint32_t addr, uint32_t rank) {
    uint32_t r; asm("mapa.shared::cluster.u32 %0, %1, %2;" : "=r"(r) : "r"(addr), "r"(rank)); return r;
}
__device__ __forceinline__ void mbar_init(uint32_t a, uint32_t cnt) {
    asm volatile("mbarrier.init.shared.b64 [%0], %1;" :: "r"(a), "r"(cnt) : "memory");
}
__device__ __forceinline__ void st_cluster_f32(uint32_t a, float v) {
    asm volatile("st.shared::cluster.f32 [%0], %1;" :: "r"(a), "f"(v) : "memory");
}
__device__ __forceinline__ void mbar_arrive_local(uint32_t a) {
    asm volatile("mbarrier.arrive.shared.b64 _, [%0];" :: "r"(a) : "memory");
}
__device__ __forceinline__ void mbar_arrive_rel_cluster(uint32_t a) {
    asm volatile("mbarrier.arrive.release.cluster.shared::cluster.b64 _, [%0];" :: "r"(a) : "memory");
}
__device__ __forceinline__ void mbar_wait(uint32_t a, uint32_t parity) {
    asm volatile(
        "{\n\t.reg .pred P;\n\t"
        "WL_%=:\n\t"
        "mbarrier.try_wait.parity.acquire.cluster.shared::cta.b64 P, [%0], %1, 0x989680;\n\t"
        "@P bra.uni WD_%=;\n\t"
        "bra.uni WL_%=;\n\t"
        "WD_%=:\n\t}"
        :: "r"(a), "r"(parity) : "memory");
}
__device__ __forceinline__ void cluster_sync_() {
    asm volatile("barrier.cluster.arrive.aligned;" ::: "memory");
    asm volatile("barrier.cluster.wait.aligned;" ::: "memory");
}
__device__ __forceinline__ float sigm(float x) {
    return __fdividef(1.f, 1.f + __expf(-x));
}
__device__ __forceinline__ float tanh_fast(float x) {
    float ax = fabsf(x);
    float e = __expf(-2.f * ax);
    float t = __fdividef(1.f - e, 1.f + e);
    return copysignf(t, x);
}

// ---- Ampere-class tensor primitives ----
__device__ __forceinline__ void ldsm_x4(uint32_t& r0, uint32_t& r1, uint32_t& r2, uint32_t& r3,
                                        uint32_t addr) {
    asm volatile("ldmatrix.sync.aligned.m8n8.x4.shared.b16 {%0,%1,%2,%3}, [%4];"
                 : "=r"(r0), "=r"(r1), "=r"(r2), "=r"(r3) : "r"(addr));
}
__device__ __forceinline__ void mma_bf16(float* d, const uint32_t* a, const uint32_t* b) {
    asm volatile("mma.sync.aligned.m16n8k16.row.col.f32.bf16.bf16.f32 "
                 "{%0,%1,%2,%3}, {%4,%5,%6,%7}, {%8,%9}, {%0,%1,%2,%3};"
                 : "+f"(d[0]), "+f"(d[1]), "+f"(d[2]), "+f"(d[3])
                 : "r"(a[0]), "r"(a[1]), "r"(a[2]), "r"(a[3]), "r"(b[0]), "r"(b[1]));
}
__device__ __forceinline__ void cp_async16(uint32_t dst, const void* src) {
    asm volatile("cp.async.cg.shared.global [%0], [%1], 16;" :: "r"(dst), "l"(src) : "memory");
}
__device__ __forceinline__ void cp_commit() { asm volatile("cp.async.commit_group;" ::: "memory"); }
__device__ __forceinline__ void cp_wait1() { asm volatile("cp.async.wait_group 1;" ::: "memory"); }
__device__ __forceinline__ void cp_wait0() { asm volatile("cp.async.wait_group 0;" ::: "memory"); }

// ---------------- bf16 hi/lo split ----------------
__global__ void cvt_split_k(const float* __restrict__ x, u16* __restrict__ hi,
                            u16* __restrict__ lo, int n4)
{
    int i = blockIdx.x * blockDim.x + threadIdx.x;
    if (i >= n4) return;
    float4 v = __ldg((const float4*)x + i);
    __nv_bfloat16 h0 = __float2bfloat16(v.x), h1 = __float2bfloat16(v.y);
    __nv_bfloat16 h2 = __float2bfloat16(v.z), h3 = __float2bfloat16(v.w);
    __nv_bfloat16 l0 = __float2bfloat16(v.x - __bfloat162float(h0));
    __nv_bfloat16 l1 = __float2bfloat16(v.y - __bfloat162float(h1));
    __nv_bfloat16 l2 = __float2bfloat16(v.z - __bfloat162float(h2));
    __nv_bfloat16 l3 = __float2bfloat16(v.w - __bfloat162float(h3));
    ushort4 hv = {__bfloat16_as_ushort(h0), __bfloat16_as_ushort(h1),
                  __bfloat16_as_ushort(h2), __bfloat16_as_ushort(h3)};
    ushort4 lv = {__bfloat16_as_ushort(l0), __bfloat16_as_ushort(l1),
                  __bfloat16_as_ushort(l2), __bfloat16_as_ushort(l3)};
    *(ushort4*)(hi + 4 * i) = hv;
    *(ushort4*)(lo + 4 * i) = lv;
}

// ---------------- HMMA pre-activation GEMM (3-stage) ----------------
// C[m][n] = sum_k A[idx[m]][k]*W[n][k] + bias[n]; bf16 3-term split, 36 chunks.
// Grid (4 n, 256 m, 4 z) — n fastest so the 4 n-tiles of an m-tile co-fetch A
// (L2 coalesces the gather). 3-stage cp.async, issue-before-compute.
struct TcArgs {
    const int*   idx[4];
    const float* bias[4];
    float*       C[4];
};

#define STG 32768
#define MG_SMEM (1024 + 3 * STG)

__device__ __forceinline__ uint32_t swaddr(uint32_t base, int row, int chunk) {
    uint32_t off = (uint32_t)(row * 128 + chunk * 16);
    return base + (off ^ ((off >> 3) & 0x70));
}

__global__ __launch_bounds__(256, 2)
void mma_gemm(TcArgs args, const u16* __restrict__ Eh, const u16* __restrict__ El,
              const u16* __restrict__ Wh, const u16* __restrict__ Wl)
{
    extern __shared__ char sm[];
    const int tid = threadIdx.x, lid = tid & 31, wid = tid >> 5;
    const int n0 = blockIdx.x * 128, m0 = blockIdx.y * 128, z = blockIdx.z;
    const u16* Whz = Wh + (size_t)z * WELEM;
    const u16* Wlz = Wl + (size_t)z * WELEM;
    int* idx_sm = (int*)sm;
    if (tid < 128) idx_sm[tid] = __ldg(args.idx[z] + m0 + tid);
    __syncthreads();
    const uint32_t smb = smem_u32(sm);
    const int wm = wid & 3, wn = wid >> 2;

    const int ldrow = tid >> 1, ldh = tid & 1;
    const size_t a_gr = (size_t)idx_sm[ldrow] * KDIM + ldh * 32;
    const size_t b_gr = (size_t)(n0 + ldrow) * KDIM + ldh * 32;
    uint32_t adst[4], bdst[4];
#pragma unroll
    for (int s = 0; s < 4; s++) {
        adst[s] = swaddr(smb + 1024, ldrow, ldh * 4 + s);
        bdst[s] = swaddr(smb + 1024 + 16384, ldrow, ldh * 4 + s);
    }

    float d[2][8][4];
#pragma unroll
    for (int i = 0; i < 2; i++)
#pragma unroll
        for (int j = 0; j < 8; j++)
#pragma unroll
            for (int k = 0; k < 4; k++) d[i][j][k] = 0.f;

    auto issue = [&](int c, int buf) {
        const int p = c / 12, kbase = (c % 12) * 64;
        const u16* As = (p == 1) ? El : Eh;
        const u16* Bs = (p == 2) ? Wlz : Whz;
        const u16* as = As + a_gr + kbase;
        const u16* bs = Bs + b_gr + kbase;
        const uint32_t bo = (uint32_t)(buf * STG);
#pragma unroll
        for (int s = 0; s < 4; s++) cp_async16(adst[s] + bo, as + 8 * s);
#pragma unroll
        for (int s = 0; s < 4; s++) cp_async16(bdst[s] + bo, bs + 8 * s);
        cp_commit();
    };

    const int g8 = lid & 7, grp = lid >> 3;
    const int arow_off = g8 + ((grp & 1) << 3);
    const int acol_sel = grp >> 1;
    const int brow_off = g8 + ((grp >> 1) << 3);
    const int bcol_sel = grp & 1;

    issue(0, 0);
    issue(1, 1);

#pragma unroll 1
    for (int c = 0; c < 36; c++) {
        const int buf = c % 3;
        if (c < 34) cp_wait1(); else cp_wait0();
        __syncthreads();
        if (c + 2 < 36) issue(c + 2, (c + 2) % 3);   // prefetch 2 ahead into freed buffer
        const uint32_t abase = smb + 1024 + buf * STG;
        const uint32_t bbase = abase + 16384;
#pragma unroll
        for (int kt2 = 0; kt2 < 2; kt2++) {
            uint32_t a[2][2][4];
#pragma unroll
            for (int mt = 0; mt < 2; mt++)
#pragma unroll
                for (int kk = 0; kk < 2; kk++) {
                    int kt = 2 * kt2 + kk;
                    ldsm_x4(a[mt][kk][0], a[mt][kk][1], a[mt][kk][2], a[mt][kk][3],
                            swaddr(abase, wm * 32 + mt * 16 + arow_off, 2 * kt + acol_sel));
                }
#pragma unroll
            for (int nt = 0; nt < 4; nt++) {
                uint32_t b[2][4];
#pragma unroll
                for (int kk = 0; kk < 2; kk++) {
                    int kt = 2 * kt2 + kk;
                    ldsm_x4(b[kk][0], b[kk][1], b[kk][2], b[kk][3],
                            swaddr(bbase, wn * 64 + nt * 16 + brow_off, 2 * kt + bcol_sel));
                }
#pragma unroll
                for (int mt = 0; mt < 2; mt++)
#pragma unroll
                    for (int n8 = 0; n8 < 2; n8++)
#pragma unroll
                        for (int kk = 0; kk < 2; kk++)
                            mma_bf16(d[mt][nt * 2 + n8], a[mt][kk], &b[kk][n8 * 2]);
            }
        }
        __syncthreads();
    }

    const float* bias = args.bias[z];
    float* C = args.C[z];
#pragma unroll
    for (int mt = 0; mt < 2; mt++) {
        int r0 = m0 + wm * 32 + mt * 16 + (lid >> 2);
#pragma unroll
        for (int f = 0; f < 8; f++) {
            int n = n0 + wn * 64 + f * 8 + 2 * (lid & 3);
            float2 bv = *(const float2*)(bias + n);
            float2 o0 = {d[mt][f][0] + bv.x, d[mt][f][1] + bv.y};
            float2 o1 = {d[mt][f][2] + bv.x, d[mt][f][3] + bv.y};
            *(float2*)(C + (size_t)r0 * 512 + n) = o0;
            *(float2*)(C + (size_t)(r0 + 8) * 512 + n) = o1;
        }
    }
}

// ---------------- HMMA gate GEMM + sigmoid blend (3-stage) ----------------
// logit[m][n] = concat(fo,fs)[m] . gW[n] + gb[n]; out = s*fo + (1-s)*fs.
// bf16 3-term split of A (fo/fs) and gW; K_eff = 3*512 -> 24 chunks of 64.
__global__ __launch_bounds__(256, 2)
void gate_mma(const u16* __restrict__ foh, const u16* __restrict__ fol,
              const u16* __restrict__ fsh, const u16* __restrict__ fsl,
              const u16* __restrict__ gWh, const u16* __restrict__ gWl,
              const float* __restrict__ gb, float* __restrict__ out,
              const float* __restrict__ fo, const float* __restrict__ fs)
{
    extern __shared__ char sm[];
    const int tid = threadIdx.x, lid = tid & 31, wid = tid >> 5;
    const int n0 = blockIdx.x * 128, m0 = blockIdx.y * 128;
    const uint32_t smb = smem_u32(sm);
    const int wm = wid & 3, wn = wid >> 2;

    const int ldrow = tid >> 1, ldh = tid & 1;
    uint32_t adst[4], bdst[4];
#pragma unroll
    for (int s = 0; s < 4; s++) {
        adst[s] = swaddr(smb + 1024, ldrow, ldh * 4 + s);
        bdst[s] = swaddr(smb + 1024 + 16384, ldrow, ldh * 4 + s);
    }

    float d[2][8][4];
#pragma unroll
    for (int i = 0; i < 2; i++)
#pragma unroll
        for (int j = 0; j < 8; j++)
#pragma unroll
            for (int k = 0; k < 4; k++) d[i][j][k] = 0.f;

    auto issue = [&](int c, int buf) {
        const int p = c / 8, kc = (c % 8) * 64;
        const u16* Aarr = (kc < 256) ? ((p == 1) ? fol : foh) : ((p == 1) ? fsl : fsh);
        const int acol = (kc < 256) ? kc : kc - 256;
        const u16* Bsrc = (p == 2) ? gWl : gWh;
        const u16* as = Aarr + (size_t)(m0 + ldrow) * 256 + acol + ldh * 32;
        const u16* bs = Bsrc + (size_t)(n0 + ldrow) * 512 + kc + ldh * 32;
        const uint32_t bo = (uint32_t)(buf * STG);
#pragma unroll
        for (int s = 0; s < 4; s++) cp_async16(adst[s] + bo, as + 8 * s);
#pragma unroll
        for (int s = 0; s < 4; s++) cp_async16(bdst[s] + bo, bs + 8 * s);
        cp_commit();
    };

    const int g8 = lid & 7, grp = lid >> 3;
    const int arow_off = g8 + ((grp & 1) << 3);
    const int acol_sel = grp >> 1;
    const int brow_off = g8 + ((grp >> 1) << 3);
    const int bcol_sel = grp & 1;

    issue(0, 0);
    issue(1, 1);

#pragma unroll 1
    for (int c = 0; c < 24; c++) {
        const int buf = c % 3;
        if (c < 22) cp_wait1(); else cp_wait0();
        __syncthreads();
        if (c + 2 < 24) issue(c + 2, (c + 2) % 3);
        const uint32_t abase = smb + 1024 + buf * STG;
        const uint32_t bbase = abase + 16384;
#pragma unroll
        for (int kt2 = 0; kt2 < 2; kt2++) {
            uint32_t a[2][2][4];
#pragma unroll
            for (int mt = 0; mt < 2; mt++)
#pragma unroll
                for (int kk = 0; kk < 2; kk++) {
                    int kt = 2 * kt2 + kk;
                    ldsm_x4(a[mt][kk][0], a[mt][kk][1], a[mt][kk][2], a[mt][kk][3],
                            swaddr(abase, wm * 32 + mt * 16 + arow_off, 2 * kt + acol_sel));
                }
#pragma unroll
            for (int nt = 0; nt < 4; nt++) {
                uint32_t b[2][4];
#pragma unroll
                for (int kk = 0; kk < 2; kk++) {
                    int kt = 2 * kt2 + kk;
                    ldsm_x4(b[kk][0], b[kk][1], b[kk][2], b[kk][3],
                            swaddr(bbase, wn * 64 + nt * 16 + brow_off, 2 * kt + bcol_sel));
                }
#pragma unroll
                for (int mt = 0; mt < 2; mt++)
#pragma unroll
                    for (int n8 = 0; n8 < 2; n8++)
#pragma unroll
                        for (int kk = 0; kk < 2; kk++)
                            mma_bf16(d[mt][nt * 2 + n8], a[mt][kk], &b[kk][n8 * 2]);
            }
        }
        __syncthreads();
    }

#pragma unroll
    for (int mt = 0; mt < 2; mt++) {
        int r0 = m0 + wm * 32 + mt * 16 + (lid >> 2);
#pragma unroll
        for (int f = 0; f < 8; f++) {
            int n = n0 + wn * 64 + f * 8 + 2 * (lid & 3);
            float2 bv = *(const float2*)(gb + n);
#pragma unroll
            for (int rr = 0; rr < 2; rr++) {
                int r = r0 + rr * 8;
                float2 fov = *(const float2*)(fo + (size_t)r * 256 + n);
                float2 fsv = *(const float2*)(fs + (size_t)r * 256 + n);
                float s0 = sigm(d[mt][f][2 * rr + 0] + bv.x);
                float s1 = sigm(d[mt][f][2 * rr + 1] + bv.y);
                float2 o = {s0 * fov.x + (1.f - s0) * fsv.x,
                            s1 * fov.y + (1.f - s1) * fsv.y};
                *(float2*)(out + (size_t)r * 256 + n) = o;
            }
        }
    }
}

// ---------------- BiLSTM recurrence (unchanged, proven) ----------------
__global__ __launch_bounds__(256, 1)
void lstm_k(const float* __restrict__ pwf, const float* __restrict__ pwb,
            const float* __restrict__ Wf,  const float* __restrict__ Wb,
            float* __restrict__ fo,
            const float* __restrict__ psf, const float* __restrict__ psb,
            const float* __restrict__ sWf, const float* __restrict__ sWb,
            float* __restrict__ fs)
{
    __shared__ __align__(16) float h_sh[2][128];
    __shared__ float gacc[256];
    __shared__ __align__(8) ull bars[2];
    const int t = threadIdx.x;
    const int cidg = blockIdx.x >> 1;
    const uint32_t r = ctarank();

    const float *pre, *Whh; float* outb; int L, dir, seq;
    if (cidg < 64) {
        dir = cidg & 1; seq = cidg >> 1;
        pre = dir ? pwb : pwf; Whh = dir ? Wb : Wf; outb = fo; L = 1024;
    } else {
        int c = cidg - 64;
        dir = c & 1; seq = c >> 1;
        pre = dir ? psb : psf; Whh = dir ? sWb : sWf; outb = fs; L = 64;
    }
    const int q = t >> 6, u = t & 63;
    const int grow = q * 128 + (int)r * 64 + u;

    ull w2[64];
    {
        const ulonglong2* wr = (const ulonglong2*)(Whh + (size_t)grow * 128);
#pragma unroll
        for (int i = 0; i < 32; i++) { ulonglong2 v = wr[i]; w2[2 * i] = v.x; w2[2 * i + 1] = v.y; }
    }
    if (t < 128) { h_sh[0][t] = 0.f; h_sh[1][t] = 0.f; }
    uint32_t bar0 = smem_u32(&bars[0]), bar1 = smem_u32(&bars[1]);
    if (t == 0) { mbar_init(bar0, 512); mbar_init(bar1, 512); }
    __syncthreads();
    cluster_sync_();
    const uint32_t peer = r ^ 1u;
    const uint32_t rbar0 = mapa_u32(bar0, peer), rbar1 = mapa_u32(bar1, peer);
    const uint32_t hb0 = smem_u32(&h_sh[0][0]), hb1 = smem_u32(&h_sh[1][0]);
    const size_t seqbase = (size_t)seq * L;

    int ph0 = 0, ph1 = 0;
    float c = 0.f;
    float pv0 = __ldg(pre + (seqbase + (dir ? (L - 1) : 0)) * 512 + grow);
    float pv1 = (L > 1) ? __ldg(pre + (seqbase + (dir ? (L - 2) : 1)) * 512 + grow) : 0.f;

    for (int s = 0; s < L; s++) {
        int b = s & 1;
        if (s > 0) {
            if (b) { mbar_wait(bar1, ph1); ph1 ^= 1; }
            else   { mbar_wait(bar0, ph0); ph0 ^= 1; }
        }
        const ull* h2 = (const ull*)h_sh[b];
        ull c0 = 0ULL, c1 = 0ULL, c2 = 0ULL, c3 = 0ULL;
#pragma unroll
        for (int k = 0; k < 16; k++) {
            c0 = ffma2(w2[4 * k + 0], h2[4 * k + 0], c0);
            c1 = ffma2(w2[4 * k + 1], h2[4 * k + 1], c1);
            c2 = ffma2(w2[4 * k + 2], h2[4 * k + 2], c2);
            c3 = ffma2(w2[4 * k + 3], h2[4 * k + 3], c3);
        }
        float2 s0 = unpack2(c0), s1 = unpack2(c1), s2 = unpack2(c2), s3 = unpack2(c3);
        float acc = pv0 + ((s0.x + s0.y) + (s1.x + s1.y)) + ((s2.x + s2.y) + (s3.x + s3.y));
        pv0 = pv1;
        int sp2 = s + 2;
        pv1 = (sp2 < L) ? __ldg(pre + (seqbase + (dir ? (L - 1 - sp2) : sp2)) * 512 + grow) : 0.f;
        gacc[t] = (q == 2) ? tanh_fast(acc) : sigm(acc);
        __syncthreads();
        int nb = b ^ 1;
        bool last = (s == L - 1);
        if (t < 64) {
            float gi = gacc[t], gf = gacc[64 + t], gg = gacc[128 + t], go = gacc[192 + t];
            c = gf * c + gi * gg;
            float h = go * tanh_fast(c);
            int j = (int)r * 64 + t;
            int tp = dir ? (L - 1 - s) : s;
            outb[(seqbase + tp) * 256 + dir * 128 + j] = h;
            if (!last) {
                h_sh[nb][j] = h;
                st_cluster_f32(mapa_u32((nb ? hb1 : hb0) + 4u * j, peer), h);
            }
        }
        if (!last) {
            mbar_arrive_local(nb ? bar1 : bar0);
            mbar_arrive_rel_cluster(nb ? rbar1 : rbar0);
        }
    }
    cluster_sync_();
}

extern "C" void kernel_launch(void* const* d_in, const int* in_sizes, int n_in,
                              void* d_out, int out_size)
{
    (void)in_sizes; (void)out_size;
    const int off = (n_in >= 18) ? 1 : 0;
    const int*   widx   = (const int*)d_in[0];
    const int*   sidx   = (const int*)d_in[1];
    const float* E      = (const float*)d_in[2 + off];
    const float* Wih_f  = (const float*)d_in[3 + off];
    const float* Whh_f  = (const float*)d_in[4 + off];
    const float* b_f    = (const float*)d_in[5 + off];
    const float* Wih_b  = (const float*)d_in[6 + off];
    const float* Whh_b  = (const float*)d_in[7 + off];
    const float* b_b    = (const float*)d_in[8 + off];
    const float* sWih_f = (const float*)d_in[9 + off];
    const float* sWhh_f = (const float*)d_in[10 + off];
    const float* sb_f   = (const float*)d_in[11 + off];
    const float* sWih_b = (const float*)d_in[12 + off];
    const float* sWhh_b = (const float*)d_in[13 + off];
    const float* sb_b   = (const float*)d_in[14 + off];
    const float* gW     = (const float*)d_in[15 + off];
    const float* gb     = (const float*)d_in[16 + off];
    float* out = (float*)d_out;

    float *pwf, *pwb, *psf, *psb, *fo, *fs;
    u16 *eh, *el, *wh, *wl, *foh, *fol, *fsh, *fsl, *gwh, *gwl;
    cudaGetSymbolAddress((void**)&pwf, g_pre_wf);
    cudaGetSymbolAddress((void**)&pwb, g_pre_wb);
    cudaGetSymbolAddress((void**)&psf, g_pre_sf);
    cudaGetSymbolAddress((void**)&psb, g_pre_sb);
    cudaGetSymbolAddress((void**)&fo, g_fo);
    cudaGetSymbolAddress((void**)&fs, g_fs);
    cudaGetSymbolAddress((void**)&eh, g_Eh);
    cudaGetSymbolAddress((void**)&el, g_El);
    cudaGetSymbolAddress((void**)&wh, g_Wh);
    cudaGetSymbolAddress((void**)&wl, g_Wl);
    cudaGetSymbolAddress((void**)&foh, g_foh);
    cudaGetSymbolAddress((void**)&fol, g_fol);
    cudaGetSymbolAddress((void**)&fsh, g_fsh);
    cudaGetSymbolAddress((void**)&fsl, g_fsl);
    cudaGetSymbolAddress((void**)&gwh, g_gWh);
    cudaGetSymbolAddress((void**)&gwl, g_gWl);

    // bf16 hi/lo splits (E, 4 input-proj W, gate W)
    const int n4E = EELEM / 4;
    cvt_split_k<<<(n4E + 255) / 256, 256>>>(E, eh, el, n4E);
    const int n4W = WELEM / 4;
    cvt_split_k<<<(n4W + 255) / 256, 256>>>(Wih_f,  wh + 0 * WELEM, wl + 0 * WELEM, n4W);
    cvt_split_k<<<(n4W + 255) / 256, 256>>>(Wih_b,  wh + 1 * WELEM, wl + 1 * WELEM, n4W);
    cvt_split_k<<<(n4W + 255) / 256, 256>>>(sWih_f, wh + 2 * WELEM, wl + 2 * WELEM, n4W);
    cvt_split_k<<<(n4W + 255) / 256, 256>>>(sWih_b, wh + 3 * WELEM, wl + 3 * WELEM, n4W);
    const int n4G = (256 * 512) / 4;
    cvt_split_k<<<(n4G + 255) / 256, 256>>>(gW, gwh, gwl, n4G);

    // 4 pre-activation GEMMs on HMMA (grid: n fastest for L2 A-reuse)
    TcArgs ta;
    ta.idx[0] = widx; ta.idx[1] = widx; ta.idx[2] = sidx; ta.idx[3] = sidx;
    ta.bias[0] = b_f; ta.bias[1] = b_b; ta.bias[2] = sb_f; ta.bias[3] = sb_b;
    ta.C[0] = pwf;    ta.C[1] = pwb;    ta.C[2] = psf;    ta.C[3] = psb;
    cudaFuncSetAttribute(mma_gemm, cudaFuncAttributeMaxDynamicSharedMemorySize, MG_SMEM);
    mma_gemm<<<dim3(4, MTOK / 128, 4), 256, MG_SMEM>>>(ta, eh, el, wh, wl);

    // merged BiLSTM
    {
        cudaLaunchConfig_t cfg = {};
        cfg.gridDim = dim3((64 + 1024) * 2, 1, 1);
        cfg.blockDim = dim3(256, 1, 1);
        cfg.dynamicSmemBytes = 0;
        cfg.stream = 0;
        cudaLaunchAttribute attr[1];
        attr[0].id = cudaLaunchAttributeClusterDimension;
        attr[0].val.clusterDim.x = 2; attr[0].val.clusterDim.y = 1; attr[0].val.clusterDim.z = 1;
        cfg.attrs = attr; cfg.numAttrs = 1;
        cudaLaunchKernelEx(&cfg, lstm_k, (const float*)pwf, (const float*)pwb, Whh_f, Whh_b, fo,
                           (const float*)psf, (const float*)psb, sWhh_f, sWhh_b, fs);
    }

    // fo/fs splits, then gate GEMM + blend on HMMA
    const int n4F = (MTOK * 256) / 4;
    cvt_split_k<<<(n4F + 255) / 256, 256>>>(fo, foh, fol, n4F);
    cvt_split_k<<<(n4F + 255) / 256, 256>>>(fs, fsh, fsl, n4F);
    cudaFuncSetAttribute(gate_mma, cudaFuncAttributeMaxDynamicSharedMemorySize, MG_SMEM);
    gate_mma<<<dim3(2, MTOK / 128, 1), 256, MG_SMEM>>>(foh, fol, fsh, fsl, gwh, gwl, gb, out, fo, fs);
}